// round 2
// baseline (speedup 1.0000x reference)
#include <cuda_runtime.h>
#include <math.h>
#include <stdint.h>

// ---------------- problem constants ----------------
static constexpr int D_MODEL   = 1024;
static constexpr int L_SEQ     = 2048;
static constexpr int BATCH     = 4;
static constexpr int NHEADS    = 16;
static constexpr int HDIM      = 64;
static constexpr int FF_HIDDEN = 2048;
static constexpr int M_ROWS    = BATCH * L_SEQ;   // 8192

// ---------------- scratch (__device__ globals; no cudaMalloc allowed) ------
__device__ float g_h  [(size_t)M_ROWS * D_MODEL];          // 32 MB  (LN output)
__device__ float g_qkv[(size_t)M_ROWS * 3 * D_MODEL];      // 96 MB
__device__ float g_S  [(size_t)BATCH * NHEADS * L_SEQ * L_SEQ]; // 1 GB
__device__ float g_ctx[(size_t)M_ROWS * D_MODEL];          // 32 MB
__device__ float g_x1 [(size_t)M_ROWS * D_MODEL];          // 32 MB
__device__ float g_ffh[(size_t)M_ROWS * FF_HIDDEN];        // 64 MB

// ---------------- small helpers ----------------
__device__ __forceinline__ float blockSum256(float v) {
    __shared__ float sm[8];
    int lane = threadIdx.x & 31, w = threadIdx.x >> 5;
    #pragma unroll
    for (int o = 16; o; o >>= 1) v += __shfl_down_sync(0xffffffffu, v, o);
    if (lane == 0) sm[w] = v;
    __syncthreads();
    v = (threadIdx.x < 8) ? sm[threadIdx.x] : 0.0f;
    if (w == 0) {
        #pragma unroll
        for (int o = 4; o; o >>= 1) v += __shfl_down_sync(0xffffffffu, v, o);
        if (lane == 0) sm[0] = v;
    }
    __syncthreads();
    float r = sm[0];
    __syncthreads();
    return r;
}

__device__ __forceinline__ float blockMax256(float v) {
    __shared__ float sm[8];
    int lane = threadIdx.x & 31, w = threadIdx.x >> 5;
    #pragma unroll
    for (int o = 16; o; o >>= 1) v = fmaxf(v, __shfl_down_sync(0xffffffffu, v, o));
    if (lane == 0) sm[w] = v;
    __syncthreads();
    v = (threadIdx.x < 8) ? sm[threadIdx.x] : -INFINITY;
    if (w == 0) {
        #pragma unroll
        for (int o = 4; o; o >>= 1) v = fmaxf(v, __shfl_down_sync(0xffffffffu, v, o));
        if (lane == 0) sm[0] = v;
    }
    __syncthreads();
    float r = sm[0];
    __syncthreads();
    return r;
}

// ---------------- LayerNorm: one block per row, 256 threads ----------------
__global__ void ln_kernel(const float* __restrict__ x,
                          const float* __restrict__ gam,
                          const float* __restrict__ bet,
                          float* __restrict__ out) {
    size_t row = blockIdx.x;
    const float4* xr = reinterpret_cast<const float4*>(x + row * D_MODEL);
    float4 v = xr[threadIdx.x];                 // 256 threads * 4 = 1024
    float s  = v.x + v.y + v.z + v.w;
    float sq = v.x*v.x + v.y*v.y + v.z*v.z + v.w*v.w;
    s  = blockSum256(s);
    sq = blockSum256(sq);
    float mu  = s * (1.0f / D_MODEL);
    float var = sq * (1.0f / D_MODEL) - mu * mu;
    float inv = rsqrtf(var + 1e-5f);
    float4 g4 = reinterpret_cast<const float4*>(gam)[threadIdx.x];
    float4 b4 = reinterpret_cast<const float4*>(bet)[threadIdx.x];
    float4 o;
    o.x = (v.x - mu) * inv * g4.x + b4.x;
    o.y = (v.y - mu) * inv * g4.y + b4.y;
    o.z = (v.z - mu) * inv * g4.z + b4.z;
    o.w = (v.w - mu) * inv * g4.w + b4.w;
    reinterpret_cast<float4*>(out + row * D_MODEL)[threadIdx.x] = o;
}

// ---------------- row softmax over 2048 elements -------------------------
__global__ void softmax_kernel(float* __restrict__ S) {
    size_t row = blockIdx.x;
    float4* p = reinterpret_cast<float4*>(S + row * (size_t)L_SEQ);
    float4 a = p[threadIdx.x];
    float4 b = p[threadIdx.x + 256];
    float m = fmaxf(fmaxf(fmaxf(a.x, a.y), fmaxf(a.z, a.w)),
                    fmaxf(fmaxf(b.x, b.y), fmaxf(b.z, b.w)));
    m = blockMax256(m);
    a.x = __expf(a.x - m); a.y = __expf(a.y - m); a.z = __expf(a.z - m); a.w = __expf(a.w - m);
    b.x = __expf(b.x - m); b.y = __expf(b.y - m); b.z = __expf(b.z - m); b.w = __expf(b.w - m);
    float s = a.x + a.y + a.z + a.w + b.x + b.y + b.z + b.w;
    s = blockSum256(s);
    float inv = 1.0f / s;
    a.x *= inv; a.y *= inv; a.z *= inv; a.w *= inv;
    b.x *= inv; b.y *= inv; b.z *= inv; b.w *= inv;
    p[threadIdx.x]       = a;
    p[threadIdx.x + 256] = b;
}

// ---------------- TF32 GEMM ------------------------------------------------
// C[M,N] = alpha * A @ op(B) (+ bias) (+ gelu | + residual)
// A row-major [M,K]; B row-major [K,N] (TRANS_B=false) or [N,K] (TRANS_B=true)
// EPI: 0 none, 1 +bias, 2 +bias then gelu, 3 +bias +residual
static constexpr int BM = 128, BN = 128, BK = 16;
static constexpr int AK = BK + 4;   // 20 floats per A-row in smem

__device__ __forceinline__ unsigned f2tf32(float x) {
    unsigned r;
    asm("cvt.rna.tf32.f32 %0, %1;" : "=r"(r) : "f"(x));
    return r;
}

__device__ __forceinline__ void cpa16(void* dst, const void* src) {
    unsigned d = (unsigned)__cvta_generic_to_shared(dst);
    asm volatile("cp.async.cg.shared.global [%0], [%1], 16;\n" :: "r"(d), "l"(src));
}
__device__ __forceinline__ void cpa16_pred(void* dst, const void* src, bool pred) {
    unsigned d = (unsigned)__cvta_generic_to_shared(dst);
    int sz = pred ? 16 : 0;
    asm volatile("cp.async.cg.shared.global [%0], [%1], 16, %2;\n" :: "r"(d), "l"(src), "r"(sz));
}
__device__ __forceinline__ void cpa_commit() { asm volatile("cp.async.commit_group;\n"); }
__device__ __forceinline__ void cpa_wait0()  { asm volatile("cp.async.wait_group 0;\n"); }

__device__ __forceinline__ void mma_tf32(float* c, const unsigned* a, const unsigned* b) {
    asm volatile(
        "mma.sync.aligned.m16n8k8.row.col.f32.tf32.tf32.f32 "
        "{%0,%1,%2,%3},{%4,%5,%6,%7},{%8,%9},{%0,%1,%2,%3};"
        : "+f"(c[0]), "+f"(c[1]), "+f"(c[2]), "+f"(c[3])
        : "r"(a[0]), "r"(a[1]), "r"(a[2]), "r"(a[3]), "r"(b[0]), "r"(b[1]));
}

template <bool TRANS_B, int EPI>
__global__ __launch_bounds__(256, 2)
void gemm_tf32(const float* __restrict__ A, int lda, long long sAb, long long sAh,
               const float* __restrict__ B, int ldb, long long sBb, long long sBh,
               float* __restrict__ C, int ldc, long long sCb, long long sCh,
               const float* __restrict__ bias, const float* __restrict__ res,
               int M, int N, int K, float alpha) {
    // batched offsets (z = b*NHEADS + h when batched; strides 0 otherwise)
    int bz = blockIdx.z;
    long long bb = bz / NHEADS, hh = bz % NHEADS;
    A += bb * sAb + hh * sAh;
    B += bb * sBb + hh * sBh;
    C += bb * sCb + hh * sCh;

    constexpr int BSR = TRANS_B ? BN : BK;
    constexpr int BSC = TRANS_B ? AK : (BN + 4);
    __shared__ float As[2][BM][AK];
    __shared__ float Bs[2][BSR][BSC];

    const int tid  = threadIdx.x;
    const int warp = tid >> 5, lane = tid & 31;
    const int wm = warp >> 2, wn = warp & 3;     // warp grid 2 (M) x 4 (N)
    const int group = lane >> 2, tq = lane & 3;
    const int rowBase = blockIdx.y * BM;
    const int colBase = blockIdx.x * BN;

    float acc[4][4][4];
    #pragma unroll
    for (int i = 0; i < 4; i++)
        #pragma unroll
        for (int j = 0; j < 4; j++)
            #pragma unroll
            for (int e = 0; e < 4; e++) acc[i][j][e] = 0.0f;

    const int ntiles = K / BK;

    auto loadTile = [&](int buf, int kt) {
        const int k0 = kt * BK;
        // A tile: 128 rows x 16 cols, 16B per thread, 2 passes
        {
            int r = (tid >> 2), c = (tid & 3) * 4;
            #pragma unroll
            for (int p = 0; p < 2; p++) {
                cpa16(&As[buf][r + p * 64][c],
                      A + (size_t)(rowBase + r + p * 64) * lda + k0 + c);
            }
        }
        if (TRANS_B) {
            // B tile as [n][k]: 128 rows (n) x 16 cols (k)
            int r = (tid >> 2), c = (tid & 3) * 4;
            #pragma unroll
            for (int p = 0; p < 2; p++) {
                cpa16(&Bs[buf][r + p * 64][c],
                      B + (size_t)(colBase + r + p * 64) * ldb + k0 + c);
            }
        } else {
            // B tile as [k][n]: 16 rows (k) x 128 cols (n)
            int r = (tid >> 5), c = (tid & 31) * 4;
            #pragma unroll
            for (int p = 0; p < 2; p++) {
                int n = colBase + c;
                cpa16_pred(&Bs[buf][r + p * 8][c],
                           B + (size_t)(k0 + r + p * 8) * ldb + n,
                           n < N);
            }
        }
        cpa_commit();
    };

    loadTile(0, 0);
    cpa_wait0();
    __syncthreads();

    for (int kt = 0; kt < ntiles; kt++) {
        int buf = kt & 1;
        if (kt + 1 < ntiles) loadTile(buf ^ 1, kt + 1);

        #pragma unroll
        for (int ks = 0; ks < 2; ks++) {
            unsigned af[4][4], bf[4][2];
            #pragma unroll
            for (int mt = 0; mt < 4; mt++) {
                int r = wm * 64 + mt * 16 + group;
                int c = ks * 8 + tq;
                af[mt][0] = f2tf32(As[buf][r][c]);
                af[mt][1] = f2tf32(As[buf][r + 8][c]);
                af[mt][2] = f2tf32(As[buf][r][c + 4]);
                af[mt][3] = f2tf32(As[buf][r + 8][c + 4]);
            }
            #pragma unroll
            for (int nt = 0; nt < 4; nt++) {
                int n = wn * 32 + nt * 8 + group;
                int k = ks * 8 + tq;
                if (TRANS_B) {
                    bf[nt][0] = f2tf32(Bs[buf][n][k]);
                    bf[nt][1] = f2tf32(Bs[buf][n][k + 4]);
                } else {
                    bf[nt][0] = f2tf32(Bs[buf][k][n]);
                    bf[nt][1] = f2tf32(Bs[buf][k + 4][n]);
                }
            }
            #pragma unroll
            for (int mt = 0; mt < 4; mt++)
                #pragma unroll
                for (int nt = 0; nt < 4; nt++)
                    mma_tf32(acc[mt][nt], af[mt], bf[nt]);
        }

        if (kt + 1 < ntiles) cpa_wait0();
        __syncthreads();
    }

    // ---------------- epilogue ----------------
    #pragma unroll
    for (int mt = 0; mt < 4; mt++) {
        #pragma unroll
        for (int nt = 0; nt < 4; nt++) {
            int r = rowBase + wm * 64 + mt * 16 + group;
            int c = colBase + wn * 32 + nt * 8 + tq * 2;
            #pragma unroll
            for (int half = 0; half < 2; half++) {      // c0/c1 (row r), c2/c3 (row r+8)
                int rr = r + half * 8;
                float* crow = C + (size_t)rr * ldc;
                #pragma unroll
                for (int e = 0; e < 2; e++) {
                    int cc = c + e;
                    if (cc >= N) continue;
                    float v = acc[mt][nt][half * 2 + e] * alpha;
                    if (EPI >= 1) v += bias[cc];
                    if (EPI == 2) v = v * normcdff(v);           // exact GELU
                    if (EPI == 3) v += res[(size_t)rr * ldc + cc];
                    crow[cc] = v;
                }
            }
        }
    }
}

// ---------------- launch ----------------
extern "C" void kernel_launch(void* const* d_in, const int* in_sizes, int n_in,
                              void* d_out, int out_size) {
    (void)in_sizes; (void)n_in; (void)out_size;
    const float* x     = (const float*)d_in[0];
    const float* qkv_w = (const float*)d_in[1];
    const float* qkv_b = (const float*)d_in[2];
    const float* out_w = (const float*)d_in[3];
    const float* out_b = (const float*)d_in[4];
    const float* ff1_w = (const float*)d_in[5];
    const float* ff1_b = (const float*)d_in[6];
    const float* ff2_w = (const float*)d_in[7];
    const float* ff2_b = (const float*)d_in[8];
    const float* ln1_g = (const float*)d_in[9];
    const float* ln1_b = (const float*)d_in[10];
    const float* ln2_g = (const float*)d_in[11];
    const float* ln2_b = (const float*)d_in[12];
    float* out = (float*)d_out;

    float *pH, *pQKV, *pS, *pCtx, *pX1, *pFFH;
    cudaGetSymbolAddress((void**)&pH,   g_h);
    cudaGetSymbolAddress((void**)&pQKV, g_qkv);
    cudaGetSymbolAddress((void**)&pS,   g_S);
    cudaGetSymbolAddress((void**)&pCtx, g_ctx);
    cudaGetSymbolAddress((void**)&pX1,  g_x1);
    cudaGetSymbolAddress((void**)&pFFH, g_ffh);

    const long long LL = (long long)L_SEQ;
    const float scale = 0.125f;  // HDIM^-0.5

    // 1) LN1
    ln_kernel<<<M_ROWS, 256>>>(x, ln1_g, ln1_b, pH);

    // 2) QKV = h @ qkv_w + qkv_b        [8192, 3072]
    gemm_tf32<false, 1><<<dim3(3 * D_MODEL / BN, M_ROWS / BM, 1), 256>>>(
        pH, D_MODEL, 0, 0,
        qkv_w, 3 * D_MODEL, 0, 0,
        pQKV, 3 * D_MODEL, 0, 0,
        qkv_b, nullptr, M_ROWS, 3 * D_MODEL, D_MODEL, 1.0f);

    // 3) S = scale * Q @ K^T   per (b,h); batched over z = b*16+h
    gemm_tf32<true, 0><<<dim3(L_SEQ / BN, L_SEQ / BM, BATCH * NHEADS), 256>>>(
        pQKV,            3 * D_MODEL, LL * 3 * D_MODEL, HDIM,    // Q
        pQKV + D_MODEL,  3 * D_MODEL, LL * 3 * D_MODEL, HDIM,    // K (as [N,K] rows)
        pS,              L_SEQ, (long long)NHEADS * LL * LL, LL * LL,
        nullptr, nullptr, L_SEQ, L_SEQ, HDIM, scale);

    // 4) softmax rows of S
    softmax_kernel<<<BATCH * NHEADS * L_SEQ, 256>>>(pS);

    // 5) ctx = P @ V   per (b,h)  -> [B,L,H*64] contiguous
    gemm_tf32<false, 0><<<dim3(1, L_SEQ / BM, BATCH * NHEADS), 256>>>(
        pS,                  L_SEQ, (long long)NHEADS * LL * LL, LL * LL,
        pQKV + 2 * D_MODEL,  3 * D_MODEL, LL * 3 * D_MODEL, HDIM,
        pCtx,                D_MODEL, LL * D_MODEL, HDIM,
        nullptr, nullptr, L_SEQ, HDIM, L_SEQ, 1.0f);

    // 6) x1 = ctx @ out_w + out_b + x
    gemm_tf32<false, 3><<<dim3(D_MODEL / BN, M_ROWS / BM, 1), 256>>>(
        pCtx, D_MODEL, 0, 0,
        out_w, D_MODEL, 0, 0,
        pX1, D_MODEL, 0, 0,
        out_b, x, M_ROWS, D_MODEL, D_MODEL, 1.0f);

    // 7) LN2
    ln_kernel<<<M_ROWS, 256>>>(pX1, ln2_g, ln2_b, pH);

    // 8) ffh = gelu(h @ ff1_w + ff1_b)
    gemm_tf32<false, 2><<<dim3(FF_HIDDEN / BN, M_ROWS / BM, 1), 256>>>(
        pH, D_MODEL, 0, 0,
        ff1_w, FF_HIDDEN, 0, 0,
        pFFH, FF_HIDDEN, 0, 0,
        ff1_b, nullptr, M_ROWS, FF_HIDDEN, D_MODEL, 1.0f);

    // 9) out = ffh @ ff2_w + ff2_b + x1
    gemm_tf32<false, 3><<<dim3(D_MODEL / BN, M_ROWS / BM, 1), 256>>>(
        pFFH, FF_HIDDEN, 0, 0,
        ff2_w, D_MODEL, 0, 0,
        out, D_MODEL, 0, 0,
        ff2_b, pX1, M_ROWS, D_MODEL, FF_HIDDEN, 1.0f);
}

// round 4
// speedup vs baseline: 1.2351x; 1.2351x over previous
#include <cuda_runtime.h>
#include <math.h>
#include <stdint.h>

// ---------------- problem constants ----------------
static constexpr int D_MODEL   = 1024;
static constexpr int L_SEQ     = 2048;
static constexpr int BATCH     = 4;
static constexpr int NHEADS    = 16;
static constexpr int HDIM      = 64;
static constexpr int FF_HIDDEN = 2048;
static constexpr int M_ROWS    = BATCH * L_SEQ;   // 8192

// ---------------- scratch (__device__ globals; no cudaMalloc allowed) ------
__device__ float g_h  [(size_t)M_ROWS * D_MODEL];          // 32 MB  (LN output)
__device__ float g_qkv[(size_t)M_ROWS * 3 * D_MODEL];      // 96 MB
__device__ float g_ctx[(size_t)M_ROWS * D_MODEL];          // 32 MB
__device__ float g_x1 [(size_t)M_ROWS * D_MODEL];          // 32 MB
__device__ float g_ffh[(size_t)M_ROWS * FF_HIDDEN];        // 64 MB

// ---------------- small helpers ----------------
__device__ __forceinline__ float blockSum256(float v) {
    __shared__ float sm[8];
    int lane = threadIdx.x & 31, w = threadIdx.x >> 5;
    #pragma unroll
    for (int o = 16; o; o >>= 1) v += __shfl_down_sync(0xffffffffu, v, o);
    if (lane == 0) sm[w] = v;
    __syncthreads();
    v = (threadIdx.x < 8) ? sm[threadIdx.x] : 0.0f;
    if (w == 0) {
        #pragma unroll
        for (int o = 4; o; o >>= 1) v += __shfl_down_sync(0xffffffffu, v, o);
        if (lane == 0) sm[0] = v;
    }
    __syncthreads();
    float r = sm[0];
    __syncthreads();
    return r;
}

// ---------------- LayerNorm: one block per row, 256 threads ----------------
__global__ void ln_kernel(const float* __restrict__ x,
                          const float* __restrict__ gam,
                          const float* __restrict__ bet,
                          float* __restrict__ out) {
    size_t row = blockIdx.x;
    const float4* xr = reinterpret_cast<const float4*>(x + row * D_MODEL);
    float4 v = xr[threadIdx.x];                 // 256 threads * 4 = 1024
    float s  = v.x + v.y + v.z + v.w;
    float sq = v.x*v.x + v.y*v.y + v.z*v.z + v.w*v.w;
    s  = blockSum256(s);
    sq = blockSum256(sq);
    float mu  = s * (1.0f / D_MODEL);
    float var = sq * (1.0f / D_MODEL) - mu * mu;
    float inv = rsqrtf(var + 1e-5f);
    float4 g4 = reinterpret_cast<const float4*>(gam)[threadIdx.x];
    float4 b4 = reinterpret_cast<const float4*>(bet)[threadIdx.x];
    float4 o;
    o.x = (v.x - mu) * inv * g4.x + b4.x;
    o.y = (v.y - mu) * inv * g4.y + b4.y;
    o.z = (v.z - mu) * inv * g4.z + b4.z;
    o.w = (v.w - mu) * inv * g4.w + b4.w;
    reinterpret_cast<float4*>(out + row * D_MODEL)[threadIdx.x] = o;
}

// ---------------- cp.async / mma helpers ----------------
__device__ __forceinline__ unsigned f2tf32(float x) {
    unsigned r;
    asm("cvt.rna.tf32.f32 %0, %1;" : "=r"(r) : "f"(x));
    return r;
}
__device__ __forceinline__ void cpa16(void* dst, const void* src) {
    unsigned d = (unsigned)__cvta_generic_to_shared(dst);
    asm volatile("cp.async.cg.shared.global [%0], [%1], 16;\n" :: "r"(d), "l"(src));
}
__device__ __forceinline__ void cpa16_pred(void* dst, const void* src, bool pred) {
    unsigned d = (unsigned)__cvta_generic_to_shared(dst);
    int sz = pred ? 16 : 0;
    asm volatile("cp.async.cg.shared.global [%0], [%1], 16, %2;\n" :: "r"(d), "l"(src), "r"(sz));
}
__device__ __forceinline__ void cpa_commit() { asm volatile("cp.async.commit_group;\n"); }
__device__ __forceinline__ void cpa_wait0()  { asm volatile("cp.async.wait_group 0;\n"); }

__device__ __forceinline__ void mma_tf32(float* c, const unsigned* a, const unsigned* b) {
    asm volatile(
        "mma.sync.aligned.m16n8k8.row.col.f32.tf32.tf32.f32 "
        "{%0,%1,%2,%3},{%4,%5,%6,%7},{%8,%9},{%0,%1,%2,%3};"
        : "+f"(c[0]), "+f"(c[1]), "+f"(c[2]), "+f"(c[3])
        : "r"(a[0]), "r"(a[1]), "r"(a[2]), "r"(a[3]), "r"(b[0]), "r"(b[1]));
}

// ============================================================================
// Fused flash attention: ctx[b, q, h*64+d] = softmax(Q K^T * s) V  per (b,h)
// Block: 256 threads (8 warps). Each block: 128 query rows, loops 16 key tiles
// of 128. Warp layout: warp w owns S rows [w*16, w*16+16) x all 128 key cols.
// Online softmax per lane-quad (rows live entirely within a quad).
// ============================================================================
static constexpr int FA_KPAD = 68;    // K/V smem row stride (conflict-free frags)
static constexpr int FA_PPAD = 132;   // P/Q smem row stride
static constexpr int FA_KVBYTES = 2 * 128 * FA_KPAD * 4;    // one of K or V, 2 bufs
static constexpr int FA_SMEM = 2 * FA_KVBYTES + 128 * FA_PPAD * 4;  // 206848 B

__global__ __launch_bounds__(256, 1)
void flash_attn_kernel(const float* __restrict__ qkv, float* __restrict__ ctx) {
    extern __shared__ float smem[];
    float* Ks = smem;                         // [2][128*FA_KPAD]
    float* Vs = smem + 2 * 128 * FA_KPAD;     // [2][128*FA_KPAD]
    float* Pb = Vs  + 2 * 128 * FA_KPAD;      // [128*FA_PPAD]  (Q staging, then P)

    const int tid  = threadIdx.x;
    const int warp = tid >> 5, lane = tid & 31;
    const int group = lane >> 2, tq = lane & 3;

    const int bh = blockIdx.y;                // b*16 + h
    const int b = bh >> 4, h = bh & 15;
    const int q0 = blockIdx.x * 128;

    const float* Qg = qkv + ((size_t)b * L_SEQ) * (3 * D_MODEL) + h * HDIM;
    const float* Kg = Qg + D_MODEL;
    const float* Vg = Qg + 2 * D_MODEL;

    // ---- stage Q tile into Pb ----
    {
        #pragma unroll
        for (int i = 0; i < 2; i++) {
            int e = tid * 2 + i;              // 512 = 128 rows x 4 col-segs
            int r = e >> 2, c0 = (e & 3) * 16;
            const float* src = Qg + (size_t)(q0 + r) * (3 * D_MODEL) + c0;
            float* dst = &Pb[r * FA_PPAD + c0];
            #pragma unroll
            for (int j = 0; j < 4; j++) cpa16(dst + j * 4, src + j * 4);
        }
    }
    // ---- kick off K/V tile 0 ----
    auto loadKV = [&](int buf, int t) {
        const int k0 = t * 128;
        #pragma unroll
        for (int i = 0; i < 2; i++) {
            int e = tid * 2 + i;
            int r = e >> 2, c0 = (e & 3) * 16;
            const float* ksrc = Kg + (size_t)(k0 + r) * (3 * D_MODEL) + c0;
            const float* vsrc = Vg + (size_t)(k0 + r) * (3 * D_MODEL) + c0;
            float* kdst = &Ks[buf * 128 * FA_KPAD + r * FA_KPAD + c0];
            float* vdst = &Vs[buf * 128 * FA_KPAD + r * FA_KPAD + c0];
            #pragma unroll
            for (int j = 0; j < 4; j++) cpa16(kdst + j * 4, ksrc + j * 4);
            #pragma unroll
            for (int j = 0; j < 4; j++) cpa16(vdst + j * 4, vsrc + j * 4);
        }
    };
    loadKV(0, 0);
    cpa_commit();
    cpa_wait0();
    __syncthreads();

    // ---- build Q fragments (scale folded in) ----
    unsigned qf[8][4];
    {
        const float* Qw = Pb + (size_t)(warp * 16) * FA_PPAD;
        #pragma unroll
        for (int kc = 0; kc < 8; kc++) {
            int k = kc * 8;
            qf[kc][0] = f2tf32(0.125f * Qw[(group)     * FA_PPAD + k + tq]);
            qf[kc][1] = f2tf32(0.125f * Qw[(group + 8) * FA_PPAD + k + tq]);
            qf[kc][2] = f2tf32(0.125f * Qw[(group)     * FA_PPAD + k + tq + 4]);
            qf[kc][3] = f2tf32(0.125f * Qw[(group + 8) * FA_PPAD + k + tq + 4]);
        }
    }
    __syncthreads();   // everyone done reading Q before Pb becomes P

    float* Pw = Pb + (size_t)(warp * 16) * FA_PPAD;   // this warp's P rows

    float m0 = -INFINITY, m1 = -INFINITY, l0 = 0.0f, l1 = 0.0f;
    float acc_o[8][4];
    #pragma unroll
    for (int nt = 0; nt < 8; nt++)
        #pragma unroll
        for (int e = 0; e < 4; e++) acc_o[nt][e] = 0.0f;

    const int NT = L_SEQ / 128;   // 16
    for (int t = 0; t < NT; t++) {
        const int buf = t & 1;
        if (t + 1 < NT) { loadKV(buf ^ 1, t + 1); cpa_commit(); }

        const float* Kb = Ks + buf * 128 * FA_KPAD;
        const float* Vb = Vs + buf * 128 * FA_KPAD;

        // ---- S = (scaled Q) @ K^T : 16 x 128 per warp ----
        float accs[16][4];
        #pragma unroll
        for (int nt = 0; nt < 16; nt++)
            #pragma unroll
            for (int e = 0; e < 4; e++) accs[nt][e] = 0.0f;

        #pragma unroll
        for (int kc = 0; kc < 8; kc++) {
            #pragma unroll
            for (int nt = 0; nt < 16; nt++) {
                unsigned bf[2];
                bf[0] = f2tf32(Kb[(nt * 8 + group) * FA_KPAD + kc * 8 + tq]);
                bf[1] = f2tf32(Kb[(nt * 8 + group) * FA_KPAD + kc * 8 + tq + 4]);
                mma_tf32(accs[nt], qf[kc], bf);
            }
        }

        // ---- online softmax (rows: r0=group, r1=group+8; quad shares row) ----
        float mt0 = -INFINITY, mt1 = -INFINITY;
        #pragma unroll
        for (int nt = 0; nt < 16; nt++) {
            mt0 = fmaxf(mt0, fmaxf(accs[nt][0], accs[nt][1]));
            mt1 = fmaxf(mt1, fmaxf(accs[nt][2], accs[nt][3]));
        }
        mt0 = fmaxf(mt0, __shfl_xor_sync(0xffffffffu, mt0, 1));
        mt0 = fmaxf(mt0, __shfl_xor_sync(0xffffffffu, mt0, 2));
        mt1 = fmaxf(mt1, __shfl_xor_sync(0xffffffffu, mt1, 1));
        mt1 = fmaxf(mt1, __shfl_xor_sync(0xffffffffu, mt1, 2));

        float mn0 = fmaxf(m0, mt0), mn1 = fmaxf(m1, mt1);
        float corr0 = __expf(m0 - mn0), corr1 = __expf(m1 - mn1);

        float rs0 = 0.0f, rs1 = 0.0f;
        #pragma unroll
        for (int nt = 0; nt < 16; nt++) {
            float p0 = __expf(accs[nt][0] - mn0);
            float p1 = __expf(accs[nt][1] - mn0);
            float p2 = __expf(accs[nt][2] - mn1);
            float p3 = __expf(accs[nt][3] - mn1);
            rs0 += p0 + p1;  rs1 += p2 + p3;
            int c = nt * 8 + tq * 2;
            Pw[(group)     * FA_PPAD + c]     = __uint_as_float(f2tf32(p0));
            Pw[(group)     * FA_PPAD + c + 1] = __uint_as_float(f2tf32(p1));
            Pw[(group + 8) * FA_PPAD + c]     = __uint_as_float(f2tf32(p2));
            Pw[(group + 8) * FA_PPAD + c + 1] = __uint_as_float(f2tf32(p3));
        }
        rs0 += __shfl_xor_sync(0xffffffffu, rs0, 1);
        rs0 += __shfl_xor_sync(0xffffffffu, rs0, 2);
        rs1 += __shfl_xor_sync(0xffffffffu, rs1, 1);
        rs1 += __shfl_xor_sync(0xffffffffu, rs1, 2);

        l0 = l0 * corr0 + rs0;
        l1 = l1 * corr1 + rs1;
        m0 = mn0; m1 = mn1;

        #pragma unroll
        for (int nt = 0; nt < 8; nt++) {
            acc_o[nt][0] *= corr0; acc_o[nt][1] *= corr0;
            acc_o[nt][2] *= corr1; acc_o[nt][3] *= corr1;
        }
        __syncwarp();

        // ---- acc_o += P @ V : 16 x 64 per warp ----
        #pragma unroll
        for (int kc = 0; kc < 16; kc++) {
            unsigned a[4];
            a[0] = __float_as_uint(Pw[(group)     * FA_PPAD + kc * 8 + tq]);
            a[1] = __float_as_uint(Pw[(group + 8) * FA_PPAD + kc * 8 + tq]);
            a[2] = __float_as_uint(Pw[(group)     * FA_PPAD + kc * 8 + tq + 4]);
            a[3] = __float_as_uint(Pw[(group + 8) * FA_PPAD + kc * 8 + tq + 4]);
            #pragma unroll
            for (int nt = 0; nt < 8; nt++) {
                unsigned bfv[2];
                bfv[0] = f2tf32(Vb[(kc * 8 + tq)     * FA_KPAD + nt * 8 + group]);
                bfv[1] = f2tf32(Vb[(kc * 8 + tq + 4) * FA_KPAD + nt * 8 + group]);
                mma_tf32(acc_o[nt], a, bfv);
            }
        }
        __syncwarp();

        if (t + 1 < NT) cpa_wait0();
        __syncthreads();   // all warps done with buf before it is overwritten
    }

    // ---- epilogue: divide by l, store ctx ----
    float inv0 = 1.0f / l0, inv1 = 1.0f / l1;
    size_t orow0 = ((size_t)b * L_SEQ + q0 + warp * 16 + group) * D_MODEL + h * HDIM;
    size_t orow1 = orow0 + (size_t)8 * D_MODEL;
    #pragma unroll
    for (int nt = 0; nt < 8; nt++) {
        int d = nt * 8 + tq * 2;
        float2 v0 = make_float2(acc_o[nt][0] * inv0, acc_o[nt][1] * inv0);
        float2 v1 = make_float2(acc_o[nt][2] * inv1, acc_o[nt][3] * inv1);
        *reinterpret_cast<float2*>(ctx + orow0 + d) = v0;
        *reinterpret_cast<float2*>(ctx + orow1 + d) = v1;
    }
}

// ---------------- TF32 GEMM (dense projections) ----------------------------
// C[M,N] = alpha * A @ B (+ bias) (+ gelu | + residual), B row-major [K,N]
// EPI: 0 none, 1 +bias, 2 +bias then gelu, 3 +bias +residual
static constexpr int BM = 128, BN = 128, BK = 16;
static constexpr int AK = BK + 4;

template <int EPI>
__global__ __launch_bounds__(256, 2)
void gemm_tf32(const float* __restrict__ A, int lda,
               const float* __restrict__ B, int ldb,
               float* __restrict__ C, int ldc,
               const float* __restrict__ bias, const float* __restrict__ res,
               int M, int N, int K) {
    __shared__ float As[2][BM][AK];
    __shared__ float Bs[2][BK][BN + 4];

    const int tid  = threadIdx.x;
    const int warp = tid >> 5, lane = tid & 31;
    const int wm = warp >> 2, wn = warp & 3;
    const int group = lane >> 2, tq = lane & 3;
    const int rowBase = blockIdx.y * BM;
    const int colBase = blockIdx.x * BN;

    float acc[4][4][4];
    #pragma unroll
    for (int i = 0; i < 4; i++)
        #pragma unroll
        for (int j = 0; j < 4; j++)
            #pragma unroll
            for (int e = 0; e < 4; e++) acc[i][j][e] = 0.0f;

    const int ntiles = K / BK;

    auto loadTile = [&](int bufi, int kt) {
        const int k0 = kt * BK;
        {
            int r = (tid >> 2), c = (tid & 3) * 4;
            #pragma unroll
            for (int p = 0; p < 2; p++)
                cpa16(&As[bufi][r + p * 64][c],
                      A + (size_t)(rowBase + r + p * 64) * lda + k0 + c);
        }
        {
            int r = (tid >> 5), c = (tid & 31) * 4;
            #pragma unroll
            for (int p = 0; p < 2; p++) {
                int n = colBase + c;
                cpa16_pred(&Bs[bufi][r + p * 8][c],
                           B + (size_t)(k0 + r + p * 8) * ldb + n, n < N);
            }
        }
        cpa_commit();
    };

    loadTile(0, 0);
    cpa_wait0();
    __syncthreads();

    for (int kt = 0; kt < ntiles; kt++) {
        int bufi = kt & 1;
        if (kt + 1 < ntiles) loadTile(bufi ^ 1, kt + 1);

        #pragma unroll
        for (int ks = 0; ks < 2; ks++) {
            unsigned af[4][4], bf[4][2];
            #pragma unroll
            for (int mt = 0; mt < 4; mt++) {
                int r = wm * 64 + mt * 16 + group;
                int c = ks * 8 + tq;
                af[mt][0] = f2tf32(As[bufi][r][c]);
                af[mt][1] = f2tf32(As[bufi][r + 8][c]);
                af[mt][2] = f2tf32(As[bufi][r][c + 4]);
                af[mt][3] = f2tf32(As[bufi][r + 8][c + 4]);
            }
            #pragma unroll
            for (int nt = 0; nt < 4; nt++) {
                int n = wn * 32 + nt * 8 + group;
                int k = ks * 8 + tq;
                bf[nt][0] = f2tf32(Bs[bufi][k][n]);
                bf[nt][1] = f2tf32(Bs[bufi][k + 4][n]);
            }
            #pragma unroll
            for (int mt = 0; mt < 4; mt++)
                #pragma unroll
                for (int nt = 0; nt < 4; nt++)
                    mma_tf32(acc[mt][nt], af[mt], bf[nt]);
        }

        if (kt + 1 < ntiles) cpa_wait0();
        __syncthreads();
    }

    #pragma unroll
    for (int mt = 0; mt < 4; mt++) {
        #pragma unroll
        for (int nt = 0; nt < 4; nt++) {
            int r = rowBase + wm * 64 + mt * 16 + group;
            int c = colBase + wn * 32 + nt * 8 + tq * 2;
            #pragma unroll
            for (int half = 0; half < 2; half++) {
                int rr = r + half * 8;
                float* crow = C + (size_t)rr * ldc;
                #pragma unroll
                for (int e = 0; e < 2; e++) {
                    int cc = c + e;
                    if (cc >= N) continue;
                    float v = acc[mt][nt][half * 2 + e];
                    if (EPI >= 1) v += bias[cc];
                    if (EPI == 2) v = v * normcdff(v);           // exact GELU
                    if (EPI == 3) v += res[(size_t)rr * ldc + cc];
                    crow[cc] = v;
                }
            }
        }
    }
}

// ---------------- launch ----------------
extern "C" void kernel_launch(void* const* d_in, const int* in_sizes, int n_in,
                              void* d_out, int out_size) {
    (void)in_sizes; (void)n_in; (void)out_size;
    const float* x     = (const float*)d_in[0];
    const float* qkv_w = (const float*)d_in[1];
    const float* qkv_b = (const float*)d_in[2];
    const float* out_w = (const float*)d_in[3];
    const float* out_b = (const float*)d_in[4];
    const float* ff1_w = (const float*)d_in[5];
    const float* ff1_b = (const float*)d_in[6];
    const float* ff2_w = (const float*)d_in[7];
    const float* ff2_b = (const float*)d_in[8];
    const float* ln1_g = (const float*)d_in[9];
    const float* ln1_b = (const float*)d_in[10];
    const float* ln2_g = (const float*)d_in[11];
    const float* ln2_b = (const float*)d_in[12];
    float* out = (float*)d_out;

    float *pH, *pQKV, *pCtx, *pX1, *pFFH;
    cudaGetSymbolAddress((void**)&pH,   g_h);
    cudaGetSymbolAddress((void**)&pQKV, g_qkv);
    cudaGetSymbolAddress((void**)&pCtx, g_ctx);
    cudaGetSymbolAddress((void**)&pX1,  g_x1);
    cudaGetSymbolAddress((void**)&pFFH, g_ffh);

    cudaFuncSetAttribute(flash_attn_kernel,
                         cudaFuncAttributeMaxDynamicSharedMemorySize, FA_SMEM);

    // 1) LN1
    ln_kernel<<<M_ROWS, 256>>>(x, ln1_g, ln1_b, pH);

    // 2) QKV = h @ qkv_w + qkv_b        [8192, 3072]
    gemm_tf32<1><<<dim3(3 * D_MODEL / BN, M_ROWS / BM), 256>>>(
        pH, D_MODEL, qkv_w, 3 * D_MODEL, pQKV, 3 * D_MODEL,
        qkv_b, nullptr, M_ROWS, 3 * D_MODEL, D_MODEL);

    // 3) fused attention: ctx = softmax(QK^T/8) V     [B,L,1024]
    flash_attn_kernel<<<dim3(L_SEQ / 128, BATCH * NHEADS), 256, FA_SMEM>>>(
        pQKV, pCtx);

    // 4) x1 = ctx @ out_w + out_b + x
    gemm_tf32<3><<<dim3(D_MODEL / BN, M_ROWS / BM), 256>>>(
        pCtx, D_MODEL, out_w, D_MODEL, pX1, D_MODEL,
        out_b, x, M_ROWS, D_MODEL, D_MODEL);

    // 5) LN2
    ln_kernel<<<M_ROWS, 256>>>(pX1, ln2_g, ln2_b, pH);

    // 6) ffh = gelu(h @ ff1_w + ff1_b)
    gemm_tf32<2><<<dim3(FF_HIDDEN / BN, M_ROWS / BM), 256>>>(
        pH, D_MODEL, ff1_w, FF_HIDDEN, pFFH, FF_HIDDEN,
        ff1_b, nullptr, M_ROWS, FF_HIDDEN, D_MODEL);

    // 7) out = ffh @ ff2_w + ff2_b + x1
    gemm_tf32<3><<<dim3(D_MODEL / BN, M_ROWS / BM), 256>>>(
        pFFH, FF_HIDDEN, ff2_w, D_MODEL, out, D_MODEL,
        ff2_b, pX1, M_ROWS, D_MODEL, FF_HIDDEN);
}

// round 6
// speedup vs baseline: 1.4278x; 1.1560x over previous
#include <cuda_runtime.h>
#include <math.h>
#include <stdint.h>

// ---------------- problem constants ----------------
static constexpr int D_MODEL   = 1024;
static constexpr int L_SEQ     = 2048;
static constexpr int BATCH     = 4;
static constexpr int NHEADS    = 16;
static constexpr int HDIM      = 64;
static constexpr int FF_HIDDEN = 2048;
static constexpr int M_ROWS    = BATCH * L_SEQ;   // 8192

// ---------------- scratch (__device__ globals; no cudaMalloc allowed) ------
__device__ float g_h  [(size_t)M_ROWS * D_MODEL];          // 32 MB  (LN output)
__device__ float g_qkv[(size_t)M_ROWS * 3 * D_MODEL];      // 96 MB
__device__ float g_ctx[(size_t)M_ROWS * D_MODEL];          // 32 MB
__device__ float g_x1 [(size_t)M_ROWS * D_MODEL];          // 32 MB
__device__ float g_ffh[(size_t)M_ROWS * FF_HIDDEN];        // 64 MB

// ---------------- small helpers ----------------
__device__ __forceinline__ float blockSum256(float v) {
    __shared__ float sm[8];
    int lane = threadIdx.x & 31, w = threadIdx.x >> 5;
    #pragma unroll
    for (int o = 16; o; o >>= 1) v += __shfl_down_sync(0xffffffffu, v, o);
    if (lane == 0) sm[w] = v;
    __syncthreads();
    v = (threadIdx.x < 8) ? sm[threadIdx.x] : 0.0f;
    if (w == 0) {
        #pragma unroll
        for (int o = 4; o; o >>= 1) v += __shfl_down_sync(0xffffffffu, v, o);
        if (lane == 0) sm[0] = v;
    }
    __syncthreads();
    float r = sm[0];
    __syncthreads();
    return r;
}

// ---------------- LayerNorm: one block per row, 256 threads ----------------
__global__ void ln_kernel(const float* __restrict__ x,
                          const float* __restrict__ gam,
                          const float* __restrict__ bet,
                          float* __restrict__ out) {
    size_t row = blockIdx.x;
    const float4* xr = reinterpret_cast<const float4*>(x + row * D_MODEL);
    float4 v = xr[threadIdx.x];                 // 256 threads * 4 = 1024
    float s  = v.x + v.y + v.z + v.w;
    float sq = v.x*v.x + v.y*v.y + v.z*v.z + v.w*v.w;
    s  = blockSum256(s);
    sq = blockSum256(sq);
    float mu  = s * (1.0f / D_MODEL);
    float var = sq * (1.0f / D_MODEL) - mu * mu;
    float inv = rsqrtf(var + 1e-5f);
    float4 g4 = reinterpret_cast<const float4*>(gam)[threadIdx.x];
    float4 b4 = reinterpret_cast<const float4*>(bet)[threadIdx.x];
    float4 o;
    o.x = (v.x - mu) * inv * g4.x + b4.x;
    o.y = (v.y - mu) * inv * g4.y + b4.y;
    o.z = (v.z - mu) * inv * g4.z + b4.z;
    o.w = (v.w - mu) * inv * g4.w + b4.w;
    reinterpret_cast<float4*>(out + row * D_MODEL)[threadIdx.x] = o;
}

// ---------------- cp.async / mma helpers ----------------
__device__ __forceinline__ unsigned f2tf32(float x) {
    unsigned r;
    asm("cvt.rna.tf32.f32 %0, %1;" : "=r"(r) : "f"(x));
    return r;
}
__device__ __forceinline__ void cpa16(void* dst, const void* src) {
    unsigned d = (unsigned)__cvta_generic_to_shared(dst);
    asm volatile("cp.async.cg.shared.global [%0], [%1], 16;\n" :: "r"(d), "l"(src));
}
__device__ __forceinline__ void cpa_commit() { asm volatile("cp.async.commit_group;\n"); }
__device__ __forceinline__ void cpa_wait0()  { asm volatile("cp.async.wait_group 0;\n"); }

__device__ __forceinline__ void mma_tf32(float* c, const unsigned* a, const unsigned* b) {
    asm volatile(
        "mma.sync.aligned.m16n8k8.row.col.f32.tf32.tf32.f32 "
        "{%0,%1,%2,%3},{%4,%5,%6,%7},{%8,%9},{%0,%1,%2,%3};"
        : "+f"(c[0]), "+f"(c[1]), "+f"(c[2]), "+f"(c[3])
        : "r"(a[0]), "r"(a[1]), "r"(a[2]), "r"(a[3]), "r"(b[0]), "r"(b[1]));
}

// ============================================================================
// Fused flash attention: ctx[b, q, h*64+d] = softmax(Q K^T * s) V  per (b,h)
// Block: 256 threads (8 warps). Each block: 128 query rows, loops 16 key tiles
// of 128. Warp layout: warp w owns S rows [w*16, w*16+16) x all 128 key cols.
// Online softmax per lane-quad (rows live entirely within a quad).
// NOTE: operands fed to HMMA.tf32 as raw fp32 bits (HW reads only tf32 bit
// positions -> truncation rounding; error stays well under tolerance).
// ============================================================================
static constexpr int FA_KPAD = 68;    // K/V smem row stride (conflict-free frags)
static constexpr int FA_PPAD = 132;   // P/Q smem row stride
static constexpr int FA_SMEM = (4 * 128 * FA_KPAD + 128 * FA_PPAD) * 4;  // 206848 B

__global__ __launch_bounds__(256, 1)
void flash_attn_kernel(const float* __restrict__ qkv, float* __restrict__ ctx) {
    extern __shared__ float smem[];
    float* Ks = smem;                         // [2][128*FA_KPAD]
    float* Vs = smem + 2 * 128 * FA_KPAD;     // [2][128*FA_KPAD]
    float* Pb = Vs  + 2 * 128 * FA_KPAD;      // [128*FA_PPAD]  (Q staging, then P)

    const int tid  = threadIdx.x;
    const int warp = tid >> 5, lane = tid & 31;
    const int group = lane >> 2, tq = lane & 3;

    const int bh = blockIdx.y;                // b*16 + h
    const int b = bh >> 4, h = bh & 15;
    const int q0 = blockIdx.x * 128;

    const float* Qg = qkv + ((size_t)b * L_SEQ) * (3 * D_MODEL) + h * HDIM;
    const float* Kg = Qg + D_MODEL;
    const float* Vg = Qg + 2 * D_MODEL;

    // ---- stage Q tile into Pb ----
    {
        #pragma unroll
        for (int i = 0; i < 2; i++) {
            int e = tid * 2 + i;              // 512 = 128 rows x 4 col-segs
            int r = e >> 2, c0 = (e & 3) * 16;
            const float* src = Qg + (size_t)(q0 + r) * (3 * D_MODEL) + c0;
            float* dst = &Pb[r * FA_PPAD + c0];
            #pragma unroll
            for (int j = 0; j < 4; j++) cpa16(dst + j * 4, src + j * 4);
        }
    }
    // ---- kick off K/V tile 0 ----
    auto loadKV = [&](int buf, int t) {
        const int k0 = t * 128;
        #pragma unroll
        for (int i = 0; i < 2; i++) {
            int e = tid * 2 + i;
            int r = e >> 2, c0 = (e & 3) * 16;
            const float* ksrc = Kg + (size_t)(k0 + r) * (3 * D_MODEL) + c0;
            const float* vsrc = Vg + (size_t)(k0 + r) * (3 * D_MODEL) + c0;
            float* kdst = &Ks[buf * 128 * FA_KPAD + r * FA_KPAD + c0];
            float* vdst = &Vs[buf * 128 * FA_KPAD + r * FA_KPAD + c0];
            #pragma unroll
            for (int j = 0; j < 4; j++) cpa16(kdst + j * 4, ksrc + j * 4);
            #pragma unroll
            for (int j = 0; j < 4; j++) cpa16(vdst + j * 4, vsrc + j * 4);
        }
    };
    loadKV(0, 0);
    cpa_commit();
    cpa_wait0();
    __syncthreads();

    // ---- build Q fragments (scale folded in; raw bits, no cvt) ----
    unsigned qf[8][4];
    {
        const float* Qw = Pb + (size_t)(warp * 16) * FA_PPAD;
        #pragma unroll
        for (int kc = 0; kc < 8; kc++) {
            int k = kc * 8;
            qf[kc][0] = __float_as_uint(0.125f * Qw[(group)     * FA_PPAD + k + tq]);
            qf[kc][1] = __float_as_uint(0.125f * Qw[(group + 8) * FA_PPAD + k + tq]);
            qf[kc][2] = __float_as_uint(0.125f * Qw[(group)     * FA_PPAD + k + tq + 4]);
            qf[kc][3] = __float_as_uint(0.125f * Qw[(group + 8) * FA_PPAD + k + tq + 4]);
        }
    }
    __syncthreads();   // everyone done reading Q before Pb becomes P

    float* Pw = Pb + (size_t)(warp * 16) * FA_PPAD;   // this warp's P rows

    float m0 = -INFINITY, m1 = -INFINITY, l0 = 0.0f, l1 = 0.0f;
    float acc_o[8][4];
    #pragma unroll
    for (int nt = 0; nt < 8; nt++)
        #pragma unroll
        for (int e = 0; e < 4; e++) acc_o[nt][e] = 0.0f;

    const int NT = L_SEQ / 128;   // 16
    for (int t = 0; t < NT; t++) {
        const int buf = t & 1;
        if (t + 1 < NT) { loadKV(buf ^ 1, t + 1); cpa_commit(); }

        const float* Kb = Ks + buf * 128 * FA_KPAD;
        const float* Vb = Vs + buf * 128 * FA_KPAD;

        // ---- S = (scaled Q) @ K^T : 16 x 128 per warp ----
        float accs[16][4];
        #pragma unroll
        for (int nt = 0; nt < 16; nt++)
            #pragma unroll
            for (int e = 0; e < 4; e++) accs[nt][e] = 0.0f;

        #pragma unroll
        for (int kc = 0; kc < 8; kc++) {
            #pragma unroll
            for (int nt = 0; nt < 16; nt++) {
                unsigned bf[2];
                bf[0] = __float_as_uint(Kb[(nt * 8 + group) * FA_KPAD + kc * 8 + tq]);
                bf[1] = __float_as_uint(Kb[(nt * 8 + group) * FA_KPAD + kc * 8 + tq + 4]);
                mma_tf32(accs[nt], qf[kc], bf);
            }
        }

        // ---- online softmax (rows: r0=group, r1=group+8; quad shares row) ----
        float mt0 = -INFINITY, mt1 = -INFINITY;
        #pragma unroll
        for (int nt = 0; nt < 16; nt++) {
            mt0 = fmaxf(mt0, fmaxf(accs[nt][0], accs[nt][1]));
            mt1 = fmaxf(mt1, fmaxf(accs[nt][2], accs[nt][3]));
        }
        mt0 = fmaxf(mt0, __shfl_xor_sync(0xffffffffu, mt0, 1));
        mt0 = fmaxf(mt0, __shfl_xor_sync(0xffffffffu, mt0, 2));
        mt1 = fmaxf(mt1, __shfl_xor_sync(0xffffffffu, mt1, 1));
        mt1 = fmaxf(mt1, __shfl_xor_sync(0xffffffffu, mt1, 2));

        float mn0 = fmaxf(m0, mt0), mn1 = fmaxf(m1, mt1);
        float corr0 = __expf(m0 - mn0), corr1 = __expf(m1 - mn1);

        float rs0 = 0.0f, rs1 = 0.0f;
        #pragma unroll
        for (int nt = 0; nt < 16; nt++) {
            float p0 = __expf(accs[nt][0] - mn0);
            float p1 = __expf(accs[nt][1] - mn0);
            float p2 = __expf(accs[nt][2] - mn1);
            float p3 = __expf(accs[nt][3] - mn1);
            rs0 += p0 + p1;  rs1 += p2 + p3;
            int c = nt * 8 + tq * 2;
            Pw[(group)     * FA_PPAD + c]     = p0;
            Pw[(group)     * FA_PPAD + c + 1] = p1;
            Pw[(group + 8) * FA_PPAD + c]     = p2;
            Pw[(group + 8) * FA_PPAD + c + 1] = p3;
        }
        rs0 += __shfl_xor_sync(0xffffffffu, rs0, 1);
        rs0 += __shfl_xor_sync(0xffffffffu, rs0, 2);
        rs1 += __shfl_xor_sync(0xffffffffu, rs1, 1);
        rs1 += __shfl_xor_sync(0xffffffffu, rs1, 2);

        l0 = l0 * corr0 + rs0;
        l1 = l1 * corr1 + rs1;
        m0 = mn0; m1 = mn1;

        #pragma unroll
        for (int nt = 0; nt < 8; nt++) {
            acc_o[nt][0] *= corr0; acc_o[nt][1] *= corr0;
            acc_o[nt][2] *= corr1; acc_o[nt][3] *= corr1;
        }
        __syncwarp();

        // ---- acc_o += P @ V : 16 x 64 per warp ----
        #pragma unroll
        for (int kc = 0; kc < 16; kc++) {
            unsigned a[4];
            a[0] = __float_as_uint(Pw[(group)     * FA_PPAD + kc * 8 + tq]);
            a[1] = __float_as_uint(Pw[(group + 8) * FA_PPAD + kc * 8 + tq]);
            a[2] = __float_as_uint(Pw[(group)     * FA_PPAD + kc * 8 + tq + 4]);
            a[3] = __float_as_uint(Pw[(group + 8) * FA_PPAD + kc * 8 + tq + 4]);
            #pragma unroll
            for (int nt = 0; nt < 8; nt++) {
                unsigned bfv[2];
                bfv[0] = __float_as_uint(Vb[(kc * 8 + tq)     * FA_KPAD + nt * 8 + group]);
                bfv[1] = __float_as_uint(Vb[(kc * 8 + tq + 4) * FA_KPAD + nt * 8 + group]);
                mma_tf32(acc_o[nt], a, bfv);
            }
        }
        __syncwarp();

        if (t + 1 < NT) cpa_wait0();
        __syncthreads();   // all warps done with buf before it is overwritten
    }

    // ---- epilogue: divide by l, store ctx ----
    float inv0 = 1.0f / l0, inv1 = 1.0f / l1;
    size_t orow0 = ((size_t)b * L_SEQ + q0 + warp * 16 + group) * D_MODEL + h * HDIM;
    size_t orow1 = orow0 + (size_t)8 * D_MODEL;
    #pragma unroll
    for (int nt = 0; nt < 8; nt++) {
        int d = nt * 8 + tq * 2;
        float2 v0 = make_float2(acc_o[nt][0] * inv0, acc_o[nt][1] * inv0);
        float2 v1 = make_float2(acc_o[nt][2] * inv1, acc_o[nt][3] * inv1);
        *reinterpret_cast<float2*>(ctx + orow0 + d) = v0;
        *reinterpret_cast<float2*>(ctx + orow1 + d) = v1;
    }
}

// ---------------- TF32 GEMM (dense projections) ----------------------------
// C[M,N] = A @ B (+ bias) (+ gelu | + residual), B row-major [K,N]
// EPI: 1 +bias, 2 +bias then gelu, 3 +bias +residual
// N must be a multiple of 128, K a multiple of 32.
static constexpr int BM = 128, BN = 128, BK = 32;
static constexpr int AK = 36;        // A smem row stride
static constexpr int BP = 132;       // B smem row stride

template <int EPI>
__global__ __launch_bounds__(256, 2)
void gemm_tf32(const float* __restrict__ A, int lda,
               const float* __restrict__ B, int ldb,
               float* __restrict__ C, int ldc,
               const float* __restrict__ bias, const float* __restrict__ res,
               int M, int N, int K) {
    __shared__ float As[2][BM][AK];      // 36864 B
    __shared__ float Bs[2][BK][BP];      // 33792 B

    const int tid  = threadIdx.x;
    const int warp = tid >> 5, lane = tid & 31;
    const int wm = warp >> 2, wn = warp & 3;     // 2 x 4 warp grid, 64x32 each
    const int group = lane >> 2, tq = lane & 3;
    const int rowBase = blockIdx.y * BM;
    const int colBase = blockIdx.x * BN;

    float acc[4][4][4];
    #pragma unroll
    for (int i = 0; i < 4; i++)
        #pragma unroll
        for (int j = 0; j < 4; j++)
            #pragma unroll
            for (int e = 0; e < 4; e++) acc[i][j][e] = 0.0f;

    const int ntiles = K / BK;

    auto loadTile = [&](int bufi, int kt) {
        const int k0 = kt * BK;
        {   // A tile: 128 rows x 32 cols
            int r = tid >> 3, c = (tid & 7) * 4;
            #pragma unroll
            for (int p = 0; p < 4; p++)
                cpa16(&As[bufi][r + p * 32][c],
                      A + (size_t)(rowBase + r + p * 32) * lda + k0 + c);
        }
        {   // B tile: 32 rows x 128 cols
            int r = tid >> 5, c = (tid & 31) * 4;
            #pragma unroll
            for (int p = 0; p < 4; p++)
                cpa16(&Bs[bufi][r + p * 8][c],
                      B + (size_t)(k0 + r + p * 8) * ldb + colBase + c);
        }
        cpa_commit();
    };

    loadTile(0, 0);
    cpa_wait0();
    __syncthreads();

    for (int kt = 0; kt < ntiles; kt++) {
        int bufi = kt & 1;
        if (kt + 1 < ntiles) loadTile(bufi ^ 1, kt + 1);

        #pragma unroll
        for (int ks = 0; ks < 4; ks++) {
            unsigned af[4][4], bf[4][2];
            #pragma unroll
            for (int mt = 0; mt < 4; mt++) {
                int r = wm * 64 + mt * 16 + group;
                int c = ks * 8 + tq;
                af[mt][0] = __float_as_uint(As[bufi][r][c]);
                af[mt][1] = __float_as_uint(As[bufi][r + 8][c]);
                af[mt][2] = __float_as_uint(As[bufi][r][c + 4]);
                af[mt][3] = __float_as_uint(As[bufi][r + 8][c + 4]);
            }
            #pragma unroll
            for (int nt = 0; nt < 4; nt++) {
                int n = wn * 32 + nt * 8 + group;
                int k = ks * 8 + tq;
                bf[nt][0] = __float_as_uint(Bs[bufi][k][n]);
                bf[nt][1] = __float_as_uint(Bs[bufi][k + 4][n]);
            }
            #pragma unroll
            for (int mt = 0; mt < 4; mt++)
                #pragma unroll
                for (int nt = 0; nt < 4; nt++)
                    mma_tf32(acc[mt][nt], af[mt], bf[nt]);
        }

        if (kt + 1 < ntiles) cpa_wait0();
        __syncthreads();
    }

    // ---------------- epilogue ----------------
    #pragma unroll
    for (int mt = 0; mt < 4; mt++) {
        #pragma unroll
        for (int nt = 0; nt < 4; nt++) {
            int r = rowBase + wm * 64 + mt * 16 + group;
            int c = colBase + wn * 32 + nt * 8 + tq * 2;
            #pragma unroll
            for (int half = 0; half < 2; half++) {
                int rr = r + half * 8;
                float* crow = C + (size_t)rr * ldc;
                #pragma unroll
                for (int e = 0; e < 2; e++) {
                    int cc = c + e;
                    float v = acc[mt][nt][half * 2 + e];
                    v += bias[cc];
                    if (EPI == 2) v = v * normcdff(v);           // exact GELU
                    if (EPI == 3) v += res[(size_t)rr * ldc + cc];
                    crow[cc] = v;
                }
            }
        }
    }
}

// ---------------- launch ----------------
extern "C" void kernel_launch(void* const* d_in, const int* in_sizes, int n_in,
                              void* d_out, int out_size) {
    (void)in_sizes; (void)n_in; (void)out_size;
    const float* x     = (const float*)d_in[0];
    const float* qkv_w = (const float*)d_in[1];
    const float* qkv_b = (const float*)d_in[2];
    const float* out_w = (const float*)d_in[3];
    const float* out_b = (const float*)d_in[4];
    const float* ff1_w = (const float*)d_in[5];
    const float* ff1_b = (const float*)d_in[6];
    const float* ff2_w = (const float*)d_in[7];
    const float* ff2_b = (const float*)d_in[8];
    const float* ln1_g = (const float*)d_in[9];
    const float* ln1_b = (const float*)d_in[10];
    const float* ln2_g = (const float*)d_in[11];
    const float* ln2_b = (const float*)d_in[12];
    float* out = (float*)d_out;

    float *pH, *pQKV, *pCtx, *pX1, *pFFH;
    cudaGetSymbolAddress((void**)&pH,   g_h);
    cudaGetSymbolAddress((void**)&pQKV, g_qkv);
    cudaGetSymbolAddress((void**)&pCtx, g_ctx);
    cudaGetSymbolAddress((void**)&pX1,  g_x1);
    cudaGetSymbolAddress((void**)&pFFH, g_ffh);

    cudaFuncSetAttribute(flash_attn_kernel,
                         cudaFuncAttributeMaxDynamicSharedMemorySize, FA_SMEM);

    // 1) LN1
    ln_kernel<<<M_ROWS, 256>>>(x, ln1_g, ln1_b, pH);

    // 2) QKV = h @ qkv_w + qkv_b        [8192, 3072]
    gemm_tf32<1><<<dim3(3 * D_MODEL / BN, M_ROWS / BM), 256>>>(
        pH, D_MODEL, qkv_w, 3 * D_MODEL, pQKV, 3 * D_MODEL,
        qkv_b, nullptr, M_ROWS, 3 * D_MODEL, D_MODEL);

    // 3) fused attention: ctx = softmax(QK^T/8) V     [B,L,1024]
    flash_attn_kernel<<<dim3(L_SEQ / 128, BATCH * NHEADS), 256, FA_SMEM>>>(
        pQKV, pCtx);

    // 4) x1 = ctx @ out_w + out_b + x
    gemm_tf32<3><<<dim3(D_MODEL / BN, M_ROWS / BM), 256>>>(
        pCtx, D_MODEL, out_w, D_MODEL, pX1, D_MODEL,
        out_b, x, M_ROWS, D_MODEL, D_MODEL);

    // 5) LN2
    ln_kernel<<<M_ROWS, 256>>>(pX1, ln2_g, ln2_b, pH);

    // 6) ffh = gelu(h @ ff1_w + ff1_b)
    gemm_tf32<2><<<dim3(FF_HIDDEN / BN, M_ROWS / BM), 256>>>(
        pH, D_MODEL, ff1_w, FF_HIDDEN, pFFH, FF_HIDDEN,
        ff1_b, nullptr, M_ROWS, FF_HIDDEN, D_MODEL);

    // 7) out = ffh @ ff2_w + ff2_b + x1
    gemm_tf32<3><<<dim3(D_MODEL / BN, M_ROWS / BM), 256>>>(
        pFFH, FF_HIDDEN, ff2_w, D_MODEL, out, D_MODEL,
        ff2_b, pX1, M_ROWS, D_MODEL, FF_HIDDEN);
}

// round 7
// speedup vs baseline: 1.7203x; 1.2049x over previous
#include <cuda_runtime.h>
#include <cuda_fp16.h>
#include <math.h>
#include <stdint.h>

// ---------------- problem constants ----------------
static constexpr int D_MODEL   = 1024;
static constexpr int L_SEQ     = 2048;
static constexpr int BATCH     = 4;
static constexpr int NHEADS    = 16;
static constexpr int HDIM      = 64;
static constexpr int FF_HIDDEN = 2048;
static constexpr int M_ROWS    = BATCH * L_SEQ;   // 8192

// ---------------- scratch (__device__ globals; no cudaMalloc allowed) ------
__device__ __half g_h  [(size_t)M_ROWS * D_MODEL];           // LN output (half)
__device__ float  g_qkv[(size_t)M_ROWS * 3 * D_MODEL];       // fp32 (flash input)
__device__ __half g_ctx[(size_t)M_ROWS * D_MODEL];           // attention out (half)
__device__ float  g_x1 [(size_t)M_ROWS * D_MODEL];           // residual stream
__device__ __half g_ffh[(size_t)M_ROWS * FF_HIDDEN];         // gelu out (half)
// transposed half weights: qkv_w^T | out_w^T | ff1_w^T | ff2_w^T
static constexpr size_t W_QKV = 0;
static constexpr size_t W_OUT = W_QKV + (size_t)3 * D_MODEL * D_MODEL;
static constexpr size_t W_FF1 = W_OUT + (size_t)D_MODEL * D_MODEL;
static constexpr size_t W_FF2 = W_FF1 + (size_t)FF_HIDDEN * D_MODEL;
__device__ __half g_wt[W_FF2 + (size_t)D_MODEL * FF_HIDDEN];

// ---------------- weight convert+transpose: W[K,N] f32 -> Wt[N,K] half -----
__global__ void convt_kernel(const float* __restrict__ W, __half* __restrict__ Wt,
                             int K, int N) {
    __shared__ float t[32][33];
    int bx = blockIdx.x * 32, by = blockIdx.y * 32;   // n-base, k-base
    int tx = threadIdx.x, ty = threadIdx.y;           // block (32,8)
    #pragma unroll
    for (int j = 0; j < 4; j++)
        t[ty + 8 * j][tx] = W[(size_t)(by + ty + 8 * j) * N + bx + tx];
    __syncthreads();
    #pragma unroll
    for (int j = 0; j < 4; j++)
        Wt[(size_t)(bx + ty + 8 * j) * K + by + tx] = __float2half_rn(t[tx][ty + 8 * j]);
}

// ---------------- small helpers ----------------
__device__ __forceinline__ float blockSum256(float v) {
    __shared__ float sm[8];
    int lane = threadIdx.x & 31, w = threadIdx.x >> 5;
    #pragma unroll
    for (int o = 16; o; o >>= 1) v += __shfl_down_sync(0xffffffffu, v, o);
    if (lane == 0) sm[w] = v;
    __syncthreads();
    v = (threadIdx.x < 8) ? sm[threadIdx.x] : 0.0f;
    if (w == 0) {
        #pragma unroll
        for (int o = 4; o; o >>= 1) v += __shfl_down_sync(0xffffffffu, v, o);
        if (lane == 0) sm[0] = v;
    }
    __syncthreads();
    float r = sm[0];
    __syncthreads();
    return r;
}

// ---------------- LayerNorm: one block per row, 256 threads, half out ------
__global__ void ln_kernel(const float* __restrict__ x,
                          const float* __restrict__ gam,
                          const float* __restrict__ bet,
                          __half* __restrict__ out) {
    size_t row = blockIdx.x;
    const float4* xr = reinterpret_cast<const float4*>(x + row * D_MODEL);
    float4 v = xr[threadIdx.x];
    float s  = v.x + v.y + v.z + v.w;
    float sq = v.x*v.x + v.y*v.y + v.z*v.z + v.w*v.w;
    s  = blockSum256(s);
    sq = blockSum256(sq);
    float mu  = s * (1.0f / D_MODEL);
    float var = sq * (1.0f / D_MODEL) - mu * mu;
    float inv = rsqrtf(var + 1e-5f);
    float4 g4 = reinterpret_cast<const float4*>(gam)[threadIdx.x];
    float4 b4 = reinterpret_cast<const float4*>(bet)[threadIdx.x];
    __half2* orow = reinterpret_cast<__half2*>(out + row * D_MODEL);
    orow[2 * threadIdx.x]     = __floats2half2_rn((v.x - mu) * inv * g4.x + b4.x,
                                                  (v.y - mu) * inv * g4.y + b4.y);
    orow[2 * threadIdx.x + 1] = __floats2half2_rn((v.z - mu) * inv * g4.z + b4.z,
                                                  (v.w - mu) * inv * g4.w + b4.w);
}

// ---------------- cp.async / mma helpers ----------------
__device__ __forceinline__ void cpa16(void* dst, const void* src) {
    unsigned d = (unsigned)__cvta_generic_to_shared(dst);
    asm volatile("cp.async.cg.shared.global [%0], [%1], 16;\n" :: "r"(d), "l"(src));
}
__device__ __forceinline__ void cpa_commit() { asm volatile("cp.async.commit_group;\n"); }
__device__ __forceinline__ void cpa_wait0()  { asm volatile("cp.async.wait_group 0;\n"); }

__device__ __forceinline__ void mma_tf32(float* c, const unsigned* a, const unsigned* b) {
    asm volatile(
        "mma.sync.aligned.m16n8k8.row.col.f32.tf32.tf32.f32 "
        "{%0,%1,%2,%3},{%4,%5,%6,%7},{%8,%9},{%0,%1,%2,%3};"
        : "+f"(c[0]), "+f"(c[1]), "+f"(c[2]), "+f"(c[3])
        : "r"(a[0]), "r"(a[1]), "r"(a[2]), "r"(a[3]), "r"(b[0]), "r"(b[1]));
}

__device__ __forceinline__ void mma_f16(float* c, const unsigned* a, const unsigned* b) {
    asm volatile(
        "mma.sync.aligned.m16n8k16.row.col.f32.f16.f16.f32 "
        "{%0,%1,%2,%3},{%4,%5,%6,%7},{%8,%9},{%0,%1,%2,%3};"
        : "+f"(c[0]), "+f"(c[1]), "+f"(c[2]), "+f"(c[3])
        : "r"(a[0]), "r"(a[1]), "r"(a[2]), "r"(a[3]), "r"(b[0]), "r"(b[1]));
}

// ============================================================================
// Fused flash attention (fp32 tf32-mma core, unchanged) -> half ctx output
// ============================================================================
static constexpr int FA_KPAD = 68;
static constexpr int FA_PPAD = 132;
static constexpr int FA_SMEM = (4 * 128 * FA_KPAD + 128 * FA_PPAD) * 4;  // 206848 B

__global__ __launch_bounds__(256, 1)
void flash_attn_kernel(const float* __restrict__ qkv, __half* __restrict__ ctx) {
    extern __shared__ float smem[];
    float* Ks = smem;                         // [2][128*FA_KPAD]
    float* Vs = smem + 2 * 128 * FA_KPAD;     // [2][128*FA_KPAD]
    float* Pb = Vs  + 2 * 128 * FA_KPAD;      // [128*FA_PPAD]

    const int tid  = threadIdx.x;
    const int warp = tid >> 5, lane = tid & 31;
    const int group = lane >> 2, tq = lane & 3;

    const int bh = blockIdx.y;
    const int b = bh >> 4, h = bh & 15;
    const int q0 = blockIdx.x * 128;

    const float* Qg = qkv + ((size_t)b * L_SEQ) * (3 * D_MODEL) + h * HDIM;
    const float* Kg = Qg + D_MODEL;
    const float* Vg = Qg + 2 * D_MODEL;

    {
        #pragma unroll
        for (int i = 0; i < 2; i++) {
            int e = tid * 2 + i;
            int r = e >> 2, c0 = (e & 3) * 16;
            const float* src = Qg + (size_t)(q0 + r) * (3 * D_MODEL) + c0;
            float* dst = &Pb[r * FA_PPAD + c0];
            #pragma unroll
            for (int j = 0; j < 4; j++) cpa16(dst + j * 4, src + j * 4);
        }
    }
    auto loadKV = [&](int buf, int t) {
        const int k0 = t * 128;
        #pragma unroll
        for (int i = 0; i < 2; i++) {
            int e = tid * 2 + i;
            int r = e >> 2, c0 = (e & 3) * 16;
            const float* ksrc = Kg + (size_t)(k0 + r) * (3 * D_MODEL) + c0;
            const float* vsrc = Vg + (size_t)(k0 + r) * (3 * D_MODEL) + c0;
            float* kdst = &Ks[buf * 128 * FA_KPAD + r * FA_KPAD + c0];
            float* vdst = &Vs[buf * 128 * FA_KPAD + r * FA_KPAD + c0];
            #pragma unroll
            for (int j = 0; j < 4; j++) cpa16(kdst + j * 4, ksrc + j * 4);
            #pragma unroll
            for (int j = 0; j < 4; j++) cpa16(vdst + j * 4, vsrc + j * 4);
        }
    };
    loadKV(0, 0);
    cpa_commit();
    cpa_wait0();
    __syncthreads();

    unsigned qf[8][4];
    {
        const float* Qw = Pb + (size_t)(warp * 16) * FA_PPAD;
        #pragma unroll
        for (int kc = 0; kc < 8; kc++) {
            int k = kc * 8;
            qf[kc][0] = __float_as_uint(0.125f * Qw[(group)     * FA_PPAD + k + tq]);
            qf[kc][1] = __float_as_uint(0.125f * Qw[(group + 8) * FA_PPAD + k + tq]);
            qf[kc][2] = __float_as_uint(0.125f * Qw[(group)     * FA_PPAD + k + tq + 4]);
            qf[kc][3] = __float_as_uint(0.125f * Qw[(group + 8) * FA_PPAD + k + tq + 4]);
        }
    }
    __syncthreads();

    float* Pw = Pb + (size_t)(warp * 16) * FA_PPAD;

    float m0 = -INFINITY, m1 = -INFINITY, l0 = 0.0f, l1 = 0.0f;
    float acc_o[8][4];
    #pragma unroll
    for (int nt = 0; nt < 8; nt++)
        #pragma unroll
        for (int e = 0; e < 4; e++) acc_o[nt][e] = 0.0f;

    const int NT = L_SEQ / 128;
    for (int t = 0; t < NT; t++) {
        const int buf = t & 1;
        if (t + 1 < NT) { loadKV(buf ^ 1, t + 1); cpa_commit(); }

        const float* Kb = Ks + buf * 128 * FA_KPAD;
        const float* Vb = Vs + buf * 128 * FA_KPAD;

        float accs[16][4];
        #pragma unroll
        for (int nt = 0; nt < 16; nt++)
            #pragma unroll
            for (int e = 0; e < 4; e++) accs[nt][e] = 0.0f;

        #pragma unroll
        for (int kc = 0; kc < 8; kc++) {
            #pragma unroll
            for (int nt = 0; nt < 16; nt++) {
                unsigned bf[2];
                bf[0] = __float_as_uint(Kb[(nt * 8 + group) * FA_KPAD + kc * 8 + tq]);
                bf[1] = __float_as_uint(Kb[(nt * 8 + group) * FA_KPAD + kc * 8 + tq + 4]);
                mma_tf32(accs[nt], qf[kc], bf);
            }
        }

        float mt0 = -INFINITY, mt1 = -INFINITY;
        #pragma unroll
        for (int nt = 0; nt < 16; nt++) {
            mt0 = fmaxf(mt0, fmaxf(accs[nt][0], accs[nt][1]));
            mt1 = fmaxf(mt1, fmaxf(accs[nt][2], accs[nt][3]));
        }
        mt0 = fmaxf(mt0, __shfl_xor_sync(0xffffffffu, mt0, 1));
        mt0 = fmaxf(mt0, __shfl_xor_sync(0xffffffffu, mt0, 2));
        mt1 = fmaxf(mt1, __shfl_xor_sync(0xffffffffu, mt1, 1));
        mt1 = fmaxf(mt1, __shfl_xor_sync(0xffffffffu, mt1, 2));

        float mn0 = fmaxf(m0, mt0), mn1 = fmaxf(m1, mt1);
        float corr0 = __expf(m0 - mn0), corr1 = __expf(m1 - mn1);

        float rs0 = 0.0f, rs1 = 0.0f;
        #pragma unroll
        for (int nt = 0; nt < 16; nt++) {
            float p0 = __expf(accs[nt][0] - mn0);
            float p1 = __expf(accs[nt][1] - mn0);
            float p2 = __expf(accs[nt][2] - mn1);
            float p3 = __expf(accs[nt][3] - mn1);
            rs0 += p0 + p1;  rs1 += p2 + p3;
            int c = nt * 8 + tq * 2;
            Pw[(group)     * FA_PPAD + c]     = p0;
            Pw[(group)     * FA_PPAD + c + 1] = p1;
            Pw[(group + 8) * FA_PPAD + c]     = p2;
            Pw[(group + 8) * FA_PPAD + c + 1] = p3;
        }
        rs0 += __shfl_xor_sync(0xffffffffu, rs0, 1);
        rs0 += __shfl_xor_sync(0xffffffffu, rs0, 2);
        rs1 += __shfl_xor_sync(0xffffffffu, rs1, 1);
        rs1 += __shfl_xor_sync(0xffffffffu, rs1, 2);

        l0 = l0 * corr0 + rs0;
        l1 = l1 * corr1 + rs1;
        m0 = mn0; m1 = mn1;

        #pragma unroll
        for (int nt = 0; nt < 8; nt++) {
            acc_o[nt][0] *= corr0; acc_o[nt][1] *= corr0;
            acc_o[nt][2] *= corr1; acc_o[nt][3] *= corr1;
        }
        __syncwarp();

        #pragma unroll
        for (int kc = 0; kc < 16; kc++) {
            unsigned a[4];
            a[0] = __float_as_uint(Pw[(group)     * FA_PPAD + kc * 8 + tq]);
            a[1] = __float_as_uint(Pw[(group + 8) * FA_PPAD + kc * 8 + tq]);
            a[2] = __float_as_uint(Pw[(group)     * FA_PPAD + kc * 8 + tq + 4]);
            a[3] = __float_as_uint(Pw[(group + 8) * FA_PPAD + kc * 8 + tq + 4]);
            #pragma unroll
            for (int nt = 0; nt < 8; nt++) {
                unsigned bfv[2];
                bfv[0] = __float_as_uint(Vb[(kc * 8 + tq)     * FA_KPAD + nt * 8 + group]);
                bfv[1] = __float_as_uint(Vb[(kc * 8 + tq + 4) * FA_KPAD + nt * 8 + group]);
                mma_tf32(acc_o[nt], a, bfv);
            }
        }
        __syncwarp();

        if (t + 1 < NT) cpa_wait0();
        __syncthreads();
    }

    // ---- epilogue: divide by l, store half ctx ----
    float inv0 = 1.0f / l0, inv1 = 1.0f / l1;
    size_t orow0 = ((size_t)b * L_SEQ + q0 + warp * 16 + group) * D_MODEL + h * HDIM;
    size_t orow1 = orow0 + (size_t)8 * D_MODEL;
    #pragma unroll
    for (int nt = 0; nt < 8; nt++) {
        int d = nt * 8 + tq * 2;
        *reinterpret_cast<__half2*>(ctx + orow0 + d) =
            __floats2half2_rn(acc_o[nt][0] * inv0, acc_o[nt][1] * inv0);
        *reinterpret_cast<__half2*>(ctx + orow1 + d) =
            __floats2half2_rn(acc_o[nt][2] * inv1, acc_o[nt][3] * inv1);
    }
}

// ---------------- FP16 GEMM (dense projections) ----------------------------
// C[M,N] = A @ Bt^T (+ bias) (+ gelu | + residual)
// A [M,K] half row-major (K contiguous); Bt [N,K] half (K contiguous).
// EPI: 1 +bias, 2 +bias then gelu, 3 +bias +residual.  CT: float or __half.
static constexpr int BM = 128, BN = 128, BK = 32;
static constexpr int HPAD = 40;   // half elements per smem row (32 + 8 pad)

__device__ __forceinline__ void storeC(float* p, float v)  { *p = v; }
__device__ __forceinline__ void storeC(__half* p, float v) { *p = __float2half_rn(v); }

template <int EPI, typename CT>
__global__ __launch_bounds__(256, 2)
void gemm_fp16(const __half* __restrict__ A, int lda,
               const __half* __restrict__ Bt, int ldb,
               CT* __restrict__ C, int ldc,
               const float* __restrict__ bias, const float* __restrict__ res,
               int M, int N, int K) {
    __shared__ __half As[2][BM][HPAD];   // 20480 B
    __shared__ __half Bs[2][BN][HPAD];   // 20480 B  (rows = n, cols = k)

    const int tid  = threadIdx.x;
    const int warp = tid >> 5, lane = tid & 31;
    const int wm = warp >> 2, wn = warp & 3;     // 2 x 4 warp grid, 64x32 each
    const int group = lane >> 2, tq = lane & 3;
    const int rowBase = blockIdx.y * BM;
    const int colBase = blockIdx.x * BN;

    float acc[4][4][4];
    #pragma unroll
    for (int i = 0; i < 4; i++)
        #pragma unroll
        for (int j = 0; j < 4; j++)
            #pragma unroll
            for (int e = 0; e < 4; e++) acc[i][j][e] = 0.0f;

    const int ntiles = K / BK;

    auto loadTile = [&](int bufi, int kt) {
        const int k0 = kt * BK;
        #pragma unroll
        for (int i = 0; i < 2; i++) {          // A: 128 rows x 32 halfs = 512 chunks
            int e = tid * 2 + i;
            int r = e >> 2, c0 = (e & 3) * 8;
            cpa16(&As[bufi][r][c0], A + (size_t)(rowBase + r) * lda + k0 + c0);
        }
        #pragma unroll
        for (int i = 0; i < 2; i++) {          // Bt: 128 n-rows x 32 halfs
            int e = tid * 2 + i;
            int r = e >> 2, c0 = (e & 3) * 8;
            cpa16(&Bs[bufi][r][c0], Bt + (size_t)(colBase + r) * ldb + k0 + c0);
        }
        cpa_commit();
    };

    loadTile(0, 0);
    cpa_wait0();
    __syncthreads();

    for (int kt = 0; kt < ntiles; kt++) {
        int bufi = kt & 1;
        if (kt + 1 < ntiles) loadTile(bufi ^ 1, kt + 1);

        #pragma unroll
        for (int ks = 0; ks < 2; ks++) {       // two k16 steps per BK=32
            const int kb = ks * 16;
            unsigned af[4][4], bf[4][2];
            #pragma unroll
            for (int mt = 0; mt < 4; mt++) {
                int r = wm * 64 + mt * 16 + group;
                const __half* base = &As[bufi][r][kb + 2 * tq];
                af[mt][0] = *reinterpret_cast<const unsigned*>(base);
                af[mt][1] = *reinterpret_cast<const unsigned*>(base + 8 * HPAD);
                af[mt][2] = *reinterpret_cast<const unsigned*>(base + 8);
                af[mt][3] = *reinterpret_cast<const unsigned*>(base + 8 * HPAD + 8);
            }
            #pragma unroll
            for (int nt = 0; nt < 4; nt++) {
                int n = wn * 32 + nt * 8 + group;
                const __half* base = &Bs[bufi][n][kb + 2 * tq];
                bf[nt][0] = *reinterpret_cast<const unsigned*>(base);
                bf[nt][1] = *reinterpret_cast<const unsigned*>(base + 8);
            }
            #pragma unroll
            for (int mt = 0; mt < 4; mt++)
                #pragma unroll
                for (int nt = 0; nt < 4; nt++)
                    mma_f16(acc[mt][nt], af[mt], bf[nt]);
        }

        if (kt + 1 < ntiles) cpa_wait0();
        __syncthreads();
    }

    // ---------------- epilogue ----------------
    #pragma unroll
    for (int mt = 0; mt < 4; mt++) {
        #pragma unroll
        for (int nt = 0; nt < 4; nt++) {
            int r = rowBase + wm * 64 + mt * 16 + group;
            int c = colBase + wn * 32 + nt * 8 + tq * 2;
            #pragma unroll
            for (int half_ = 0; half_ < 2; half_++) {
                int rr = r + half_ * 8;
                CT* crow = C + (size_t)rr * ldc;
                #pragma unroll
                for (int e = 0; e < 2; e++) {
                    int cc = c + e;
                    float v = acc[mt][nt][half_ * 2 + e];
                    v += bias[cc];
                    if (EPI == 2) v = v * normcdff(v);           // exact GELU
                    if (EPI == 3) v += res[(size_t)rr * ldc + cc];
                    storeC(&crow[cc], v);
                }
            }
        }
    }
}

// ---------------- launch ----------------
extern "C" void kernel_launch(void* const* d_in, const int* in_sizes, int n_in,
                              void* d_out, int out_size) {
    (void)in_sizes; (void)n_in; (void)out_size;
    const float* x     = (const float*)d_in[0];
    const float* qkv_w = (const float*)d_in[1];
    const float* qkv_b = (const float*)d_in[2];
    const float* out_w = (const float*)d_in[3];
    const float* out_b = (const float*)d_in[4];
    const float* ff1_w = (const float*)d_in[5];
    const float* ff1_b = (const float*)d_in[6];
    const float* ff2_w = (const float*)d_in[7];
    const float* ff2_b = (const float*)d_in[8];
    const float* ln1_g = (const float*)d_in[9];
    const float* ln1_b = (const float*)d_in[10];
    const float* ln2_g = (const float*)d_in[11];
    const float* ln2_b = (const float*)d_in[12];
    float* out = (float*)d_out;

    __half *pH, *pCtx, *pFFH, *pW;
    float *pQKV, *pX1;
    cudaGetSymbolAddress((void**)&pH,   g_h);
    cudaGetSymbolAddress((void**)&pQKV, g_qkv);
    cudaGetSymbolAddress((void**)&pCtx, g_ctx);
    cudaGetSymbolAddress((void**)&pX1,  g_x1);
    cudaGetSymbolAddress((void**)&pFFH, g_ffh);
    cudaGetSymbolAddress((void**)&pW,   g_wt);

    cudaFuncSetAttribute(flash_attn_kernel,
                         cudaFuncAttributeMaxDynamicSharedMemorySize, FA_SMEM);

    // 0) convert + transpose weights to half  (W[K,N] -> Wt[N,K])
    convt_kernel<<<dim3(3 * D_MODEL / 32, D_MODEL / 32), dim3(32, 8)>>>(
        qkv_w, pW + W_QKV, D_MODEL, 3 * D_MODEL);
    convt_kernel<<<dim3(D_MODEL / 32, D_MODEL / 32), dim3(32, 8)>>>(
        out_w, pW + W_OUT, D_MODEL, D_MODEL);
    convt_kernel<<<dim3(FF_HIDDEN / 32, D_MODEL / 32), dim3(32, 8)>>>(
        ff1_w, pW + W_FF1, D_MODEL, FF_HIDDEN);
    convt_kernel<<<dim3(D_MODEL / 32, FF_HIDDEN / 32), dim3(32, 8)>>>(
        ff2_w, pW + W_FF2, FF_HIDDEN, D_MODEL);

    // 1) LN1 -> half h
    ln_kernel<<<M_ROWS, 256>>>(x, ln1_g, ln1_b, pH);

    // 2) QKV = h @ qkv_w + qkv_b   [8192, 3072] fp32 out
    gemm_fp16<1, float><<<dim3(3 * D_MODEL / BN, M_ROWS / BM), 256>>>(
        pH, D_MODEL, pW + W_QKV, D_MODEL, pQKV, 3 * D_MODEL,
        qkv_b, nullptr, M_ROWS, 3 * D_MODEL, D_MODEL);

    // 3) fused attention -> half ctx
    flash_attn_kernel<<<dim3(L_SEQ / 128, BATCH * NHEADS), 256, FA_SMEM>>>(
        pQKV, pCtx);

    // 4) x1 = ctx @ out_w + out_b + x
    gemm_fp16<3, float><<<dim3(D_MODEL / BN, M_ROWS / BM), 256>>>(
        pCtx, D_MODEL, pW + W_OUT, D_MODEL, pX1, D_MODEL,
        out_b, x, M_ROWS, D_MODEL, D_MODEL);

    // 5) LN2 -> half h
    ln_kernel<<<M_ROWS, 256>>>(pX1, ln2_g, ln2_b, pH);

    // 6) ffh = gelu(h @ ff1_w + ff1_b) -> half
    gemm_fp16<2, __half><<<dim3(FF_HIDDEN / BN, M_ROWS / BM), 256>>>(
        pH, D_MODEL, pW + W_FF1, D_MODEL, pFFH, FF_HIDDEN,
        ff1_b, nullptr, M_ROWS, FF_HIDDEN, D_MODEL);

    // 7) out = ffh @ ff2_w + ff2_b + x1
    gemm_fp16<3, float><<<dim3(D_MODEL / BN, M_ROWS / BM), 256>>>(
        pFFH, FF_HIDDEN, pW + W_FF2, FF_HIDDEN, out, D_MODEL,
        ff2_b, pX1, M_ROWS, D_MODEL, FF_HIDDEN);
}

// round 11
// speedup vs baseline: 2.3335x; 1.3564x over previous
#include <cuda_runtime.h>
#include <cuda_fp16.h>
#include <math.h>
#include <stdint.h>

// ---------------- problem constants ----------------
static constexpr int D_MODEL   = 1024;
static constexpr int L_SEQ     = 2048;
static constexpr int BATCH     = 4;
static constexpr int NHEADS    = 16;
static constexpr int HDIM      = 64;
static constexpr int FF_HIDDEN = 2048;
static constexpr int M_ROWS    = BATCH * L_SEQ;   // 8192

// ---------------- scratch (__device__ globals; no cudaMalloc allowed) ------
__device__ __half g_h  [(size_t)M_ROWS * D_MODEL];           // LN output (half)
__device__ __half g_qkv[(size_t)M_ROWS * 3 * D_MODEL];       // QKV (half)
__device__ __half g_ctx[(size_t)M_ROWS * D_MODEL];           // attention out (half)
__device__ float  g_x1 [(size_t)M_ROWS * D_MODEL];           // residual stream
__device__ __half g_ffh[(size_t)M_ROWS * FF_HIDDEN];         // gelu out (half)
__device__ float  g_qkvb[3 * D_MODEL];                       // qkv bias, Q part pre-scaled
// transposed half weights: qkv_w^T | out_w^T | ff1_w^T | ff2_w^T
static constexpr size_t W_QKV = 0;
static constexpr size_t W_OUT = W_QKV + (size_t)3 * D_MODEL * D_MODEL;
static constexpr size_t W_FF1 = W_OUT + (size_t)D_MODEL * D_MODEL;
static constexpr size_t W_FF2 = W_FF1 + (size_t)FF_HIDDEN * D_MODEL;
__device__ __half g_wt[W_FF2 + (size_t)D_MODEL * FF_HIDDEN];

// ------- weight convert+transpose: W[K,N] f32 -> Wt[N,K] half --------------
// Columns n < nScaleBelow are multiplied by 0.125 (folds softmax scale into Q).
__global__ void convt_kernel(const float* __restrict__ W, __half* __restrict__ Wt,
                             int K, int N, int nScaleBelow) {
    __shared__ float t[32][33];
    int bx = blockIdx.x * 32, by = blockIdx.y * 32;   // n-base, k-base
    int tx = threadIdx.x, ty = threadIdx.y;           // block (32,8)
    #pragma unroll
    for (int j = 0; j < 4; j++)
        t[ty + 8 * j][tx] = W[(size_t)(by + ty + 8 * j) * N + bx + tx];
    __syncthreads();
    #pragma unroll
    for (int j = 0; j < 4; j++) {
        int n = bx + ty + 8 * j;
        float v = t[tx][ty + 8 * j];
        if (n < nScaleBelow) v *= 0.125f;
        Wt[(size_t)n * K + by + tx] = __float2half_rn(v);
    }
}

__global__ void scale_qbias_kernel(const float* __restrict__ b, float* __restrict__ o) {
    int i = blockIdx.x * 256 + threadIdx.x;
    o[i] = b[i] * (i < D_MODEL ? 0.125f : 1.0f);
}

// ---------------- small helpers ----------------
__device__ __forceinline__ float blockSum256(float v) {
    __shared__ float sm[8];
    int lane = threadIdx.x & 31, w = threadIdx.x >> 5;
    #pragma unroll
    for (int o = 16; o; o >>= 1) v += __shfl_down_sync(0xffffffffu, v, o);
    if (lane == 0) sm[w] = v;
    __syncthreads();
    v = (threadIdx.x < 8) ? sm[threadIdx.x] : 0.0f;
    if (w == 0) {
        #pragma unroll
        for (int o = 4; o; o >>= 1) v += __shfl_down_sync(0xffffffffu, v, o);
        if (lane == 0) sm[0] = v;
    }
    __syncthreads();
    float r = sm[0];
    __syncthreads();
    return r;
}

// ---------------- LayerNorm: one block per row, 256 threads, half out ------
__global__ void ln_kernel(const float* __restrict__ x,
                          const float* __restrict__ gam,
                          const float* __restrict__ bet,
                          __half* __restrict__ out) {
    size_t row = blockIdx.x;
    const float4* xr = reinterpret_cast<const float4*>(x + row * D_MODEL);
    float4 v = xr[threadIdx.x];
    float s  = v.x + v.y + v.z + v.w;
    float sq = v.x*v.x + v.y*v.y + v.z*v.z + v.w*v.w;
    s  = blockSum256(s);
    sq = blockSum256(sq);
    float mu  = s * (1.0f / D_MODEL);
    float var = sq * (1.0f / D_MODEL) - mu * mu;
    float inv = rsqrtf(var + 1e-5f);
    float4 g4 = reinterpret_cast<const float4*>(gam)[threadIdx.x];
    float4 b4 = reinterpret_cast<const float4*>(bet)[threadIdx.x];
    __half2* orow = reinterpret_cast<__half2*>(out + row * D_MODEL);
    orow[2 * threadIdx.x]     = __floats2half2_rn((v.x - mu) * inv * g4.x + b4.x,
                                                  (v.y - mu) * inv * g4.y + b4.y);
    orow[2 * threadIdx.x + 1] = __floats2half2_rn((v.z - mu) * inv * g4.z + b4.z,
                                                  (v.w - mu) * inv * g4.w + b4.w);
}

// ---------------- cp.async / mma / ldmatrix helpers ----------------
__device__ __forceinline__ void cpa16(void* dst, const void* src) {
    unsigned d = (unsigned)__cvta_generic_to_shared(dst);
    asm volatile("cp.async.cg.shared.global [%0], [%1], 16;\n" :: "r"(d), "l"(src));
}
__device__ __forceinline__ void cpa_commit() { asm volatile("cp.async.commit_group;\n"); }
__device__ __forceinline__ void cpa_wait0()  { asm volatile("cp.async.wait_group 0;\n"); }

__device__ __forceinline__ void mma_f16(float* c, const unsigned* a, const unsigned* b) {
    asm volatile(
        "mma.sync.aligned.m16n8k16.row.col.f32.f16.f16.f32 "
        "{%0,%1,%2,%3},{%4,%5,%6,%7},{%8,%9},{%0,%1,%2,%3};"
        : "+f"(c[0]), "+f"(c[1]), "+f"(c[2]), "+f"(c[3])
        : "r"(a[0]), "r"(a[1]), "r"(a[2]), "r"(a[3]), "r"(b[0]), "r"(b[1]));
}

__device__ __forceinline__ void ldsm_x4(unsigned& r0, unsigned& r1,
                                        unsigned& r2, unsigned& r3, unsigned addr) {
    asm volatile("ldmatrix.sync.aligned.m8n8.x4.shared.b16 {%0,%1,%2,%3}, [%4];"
                 : "=r"(r0), "=r"(r1), "=r"(r2), "=r"(r3) : "r"(addr));
}
__device__ __forceinline__ void ldsm_x4_t(unsigned& r0, unsigned& r1,
                                          unsigned& r2, unsigned& r3, unsigned addr) {
    asm volatile("ldmatrix.sync.aligned.m8n8.x4.trans.shared.b16 {%0,%1,%2,%3}, [%4];"
                 : "=r"(r0), "=r"(r1), "=r"(r2), "=r"(r3) : "r"(addr));
}

// ============================================================================
// Fused flash attention, fp16 mma core.
// Per block: 128 q rows x (b,h); 16 key tiles of 128. 8 warps, each owns 16
// q rows. Q pre-scaled by 0.125 (folded into weights/bias upstream).
// Smem: K/V [2][128][72] half; Q-stage/P [128][136] half.
// ============================================================================
static constexpr int KP = 72;      // K/V smem row stride (halfs)
static constexpr int PP = 136;     // Q/P smem row stride (halfs)
static constexpr int FA_SMEM = (4 * 128 * KP + 128 * PP) * 2;   // 108544 B

__global__ __launch_bounds__(256, 1)
void flash_attn_kernel(const __half* __restrict__ qkv, __half* __restrict__ ctx) {
    extern __shared__ __half smemh[];
    __half* Ks = smemh;                        // [2][128*KP]
    __half* Vs = smemh + 2 * 128 * KP;         // [2][128*KP]
    __half* Pb = smemh + 4 * 128 * KP;         // [128*PP]

    const int tid  = threadIdx.x;
    const int warp = tid >> 5, lane = tid & 31;
    const int group = lane >> 2, tq = lane & 3;

    const int bh = blockIdx.y;
    const int b = bh >> 4, h = bh & 15;
    const int q0 = blockIdx.x * 128;

    const __half* Qg = qkv + ((size_t)b * L_SEQ) * (3 * D_MODEL) + h * HDIM;
    const __half* Kg = Qg + D_MODEL;
    const __half* Vg = Qg + 2 * D_MODEL;

    // ---- stage Q tile (128 x 64 half) into Pb ----
    #pragma unroll
    for (int i = 0; i < 4; i++) {
        int e = tid * 4 + i;                   // 1024 chunks of 16B
        int r = e >> 3, c0 = (e & 7) * 8;
        cpa16(&Pb[r * PP + c0], Qg + (size_t)(q0 + r) * (3 * D_MODEL) + c0);
    }
    auto loadKV = [&](int buf, int t) {
        const int k0 = t * 128;
        #pragma unroll
        for (int i = 0; i < 4; i++) {
            int e = tid * 4 + i;
            int r = e >> 3, c0 = (e & 7) * 8;
            cpa16(&Ks[buf * 128 * KP + r * KP + c0],
                  Kg + (size_t)(k0 + r) * (3 * D_MODEL) + c0);
            cpa16(&Vs[buf * 128 * KP + r * KP + c0],
                  Vg + (size_t)(k0 + r) * (3 * D_MODEL) + c0);
        }
    };
    loadKV(0, 0);
    cpa_commit();
    cpa_wait0();
    __syncthreads();

    // ---- Q fragments: 4 k16-steps x 4 regs ----
    unsigned qf[4][4];
    {
        const __half* Qw = Pb + (size_t)(warp * 16) * PP;
        #pragma unroll
        for (int kc = 0; kc < 4; kc++) {
            const __half* base = Qw + group * PP + kc * 16 + 2 * tq;
            qf[kc][0] = *reinterpret_cast<const unsigned*>(base);
            qf[kc][1] = *reinterpret_cast<const unsigned*>(base + 8 * PP);
            qf[kc][2] = *reinterpret_cast<const unsigned*>(base + 8);
            qf[kc][3] = *reinterpret_cast<const unsigned*>(base + 8 * PP + 8);
        }
    }
    __syncthreads();   // Q fully read before Pb becomes P

    __half* Pw = Pb + (size_t)(warp * 16) * PP;

    // ldmatrix per-thread offsets
    const int krow = (lane & 7) + ((lane >> 4) << 3);   // K: n-row within 16
    const int kcol = lane & 8;                          // K: k-tile select
    const int vrow = lane & 15;                         // V: key-row within 16
    const int vcol = (lane >> 4) << 3;                  // V: dh-tile select
    const unsigned ks_base = (unsigned)__cvta_generic_to_shared(Ks);
    const unsigned vs_base = (unsigned)__cvta_generic_to_shared(Vs);

    float m0 = -INFINITY, m1 = -INFINITY, l0 = 0.0f, l1 = 0.0f;
    float acc_o[8][4];
    #pragma unroll
    for (int nt = 0; nt < 8; nt++)
        #pragma unroll
        for (int e = 0; e < 4; e++) acc_o[nt][e] = 0.0f;

    const int NT = L_SEQ / 128;   // 16
    for (int t = 0; t < NT; t++) {
        const int buf = t & 1;
        if (t + 1 < NT) { loadKV(buf ^ 1, t + 1); cpa_commit(); }

        const unsigned kb_base = ks_base + buf * 128 * KP * 2;
        const unsigned vb_base = vs_base + buf * 128 * KP * 2;

        // ---- S = Qs @ K^T : 16 x 128 per warp ----
        float accs[16][4];
        #pragma unroll
        for (int nt = 0; nt < 16; nt++)
            #pragma unroll
            for (int e = 0; e < 4; e++) accs[nt][e] = 0.0f;

        #pragma unroll
        for (int ks = 0; ks < 4; ks++) {
            #pragma unroll
            for (int np = 0; np < 8; np++) {      // key n-pairs of 16
                unsigned b0, b1, b2, b3;
                unsigned addr = kb_base +
                    ((np * 16 + krow) * KP + ks * 16 + kcol) * 2;
                ldsm_x4(b0, b1, b2, b3, addr);
                unsigned bA[2] = {b0, b1}, bB[2] = {b2, b3};
                mma_f16(accs[2 * np],     qf[ks], bA);
                mma_f16(accs[2 * np + 1], qf[ks], bB);
            }
        }

        // ---- online softmax (rows group / group+8; quad shares row) ----
        float mt0 = -INFINITY, mt1 = -INFINITY;
        #pragma unroll
        for (int nt = 0; nt < 16; nt++) {
            mt0 = fmaxf(mt0, fmaxf(accs[nt][0], accs[nt][1]));
            mt1 = fmaxf(mt1, fmaxf(accs[nt][2], accs[nt][3]));
        }
        mt0 = fmaxf(mt0, __shfl_xor_sync(0xffffffffu, mt0, 1));
        mt0 = fmaxf(mt0, __shfl_xor_sync(0xffffffffu, mt0, 2));
        mt1 = fmaxf(mt1, __shfl_xor_sync(0xffffffffu, mt1, 1));
        mt1 = fmaxf(mt1, __shfl_xor_sync(0xffffffffu, mt1, 2));

        float mn0 = fmaxf(m0, mt0), mn1 = fmaxf(m1, mt1);
        float corr0 = __expf(m0 - mn0), corr1 = __expf(m1 - mn1);

        float rs0 = 0.0f, rs1 = 0.0f;
        #pragma unroll
        for (int nt = 0; nt < 16; nt++) {
            float p0 = __expf(accs[nt][0] - mn0);
            float p1 = __expf(accs[nt][1] - mn0);
            float p2 = __expf(accs[nt][2] - mn1);
            float p3 = __expf(accs[nt][3] - mn1);
            rs0 += p0 + p1;  rs1 += p2 + p3;
            int c = nt * 8 + tq * 2;
            *reinterpret_cast<__half2*>(&Pw[(group)     * PP + c]) = __floats2half2_rn(p0, p1);
            *reinterpret_cast<__half2*>(&Pw[(group + 8) * PP + c]) = __floats2half2_rn(p2, p3);
        }
        rs0 += __shfl_xor_sync(0xffffffffu, rs0, 1);
        rs0 += __shfl_xor_sync(0xffffffffu, rs0, 2);
        rs1 += __shfl_xor_sync(0xffffffffu, rs1, 1);
        rs1 += __shfl_xor_sync(0xffffffffu, rs1, 2);

        l0 = l0 * corr0 + rs0;
        l1 = l1 * corr1 + rs1;
        m0 = mn0; m1 = mn1;

        #pragma unroll
        for (int nt = 0; nt < 8; nt++) {
            acc_o[nt][0] *= corr0; acc_o[nt][1] *= corr0;
            acc_o[nt][2] *= corr1; acc_o[nt][3] *= corr1;
        }
        __syncwarp();

        // ---- acc_o += P @ V : 16 x 64 per warp ----
        #pragma unroll
        for (int kb = 0; kb < 8; kb++) {          // key k16 steps
            unsigned a[4];
            const __half* pbase = Pw + group * PP + kb * 16 + 2 * tq;
            a[0] = *reinterpret_cast<const unsigned*>(pbase);
            a[1] = *reinterpret_cast<const unsigned*>(pbase + 8 * PP);
            a[2] = *reinterpret_cast<const unsigned*>(pbase + 8);
            a[3] = *reinterpret_cast<const unsigned*>(pbase + 8 * PP + 8);
            #pragma unroll
            for (int np = 0; np < 4; np++) {      // dh n-pairs of 16
                unsigned b0, b1, b2, b3;
                unsigned addr = vb_base +
                    ((kb * 16 + vrow) * KP + np * 16 + vcol) * 2;
                ldsm_x4_t(b0, b1, b2, b3, addr);
                unsigned bA[2] = {b0, b1}, bB[2] = {b2, b3};
                mma_f16(acc_o[2 * np],     a, bA);
                mma_f16(acc_o[2 * np + 1], a, bB);
            }
        }
        __syncwarp();

        if (t + 1 < NT) cpa_wait0();
        __syncthreads();
    }

    // ---- epilogue: divide by l, store half ctx ----
    float inv0 = 1.0f / l0, inv1 = 1.0f / l1;
    size_t orow0 = ((size_t)b * L_SEQ + q0 + warp * 16 + group) * D_MODEL + h * HDIM;
    size_t orow1 = orow0 + (size_t)8 * D_MODEL;
    #pragma unroll
    for (int nt = 0; nt < 8; nt++) {
        int d = nt * 8 + tq * 2;
        *reinterpret_cast<__half2*>(ctx + orow0 + d) =
            __floats2half2_rn(acc_o[nt][0] * inv0, acc_o[nt][1] * inv0);
        *reinterpret_cast<__half2*>(ctx + orow1 + d) =
            __floats2half2_rn(acc_o[nt][2] * inv1, acc_o[nt][3] * inv1);
    }
}

// ---------------- FP16 GEMM (dense projections) ----------------------------
// C[M,N] = A @ Bt^T (+ bias) (+ gelu | + residual)
// A [M,K] half row-major; Bt [N,K] half. EPI: 1 bias, 2 bias+gelu, 3 bias+res.
static constexpr int BM = 128, BN = 128, BK = 32;
static constexpr int HPAD = 40;

__device__ __forceinline__ void storeC(float* p, float v)  { *p = v; }
__device__ __forceinline__ void storeC(__half* p, float v) { *p = __float2half_rn(v); }

template <int EPI, typename CT>
__global__ __launch_bounds__(256, 2)
void gemm_fp16(const __half* __restrict__ A, int lda,
               const __half* __restrict__ Bt, int ldb,
               CT* __restrict__ C, int ldc,
               const float* __restrict__ bias, const float* __restrict__ res,
               int M, int N, int K) {
    __shared__ __half As[2][BM][HPAD];
    __shared__ __half Bs[2][BN][HPAD];

    const int tid  = threadIdx.x;
    const int warp = tid >> 5, lane = tid & 31;
    const int wm = warp >> 2, wn = warp & 3;
    const int group = lane >> 2, tq = lane & 3;
    const int rowBase = blockIdx.y * BM;
    const int colBase = blockIdx.x * BN;

    float acc[4][4][4];
    #pragma unroll
    for (int i = 0; i < 4; i++)
        #pragma unroll
        for (int j = 0; j < 4; j++)
            #pragma unroll
            for (int e = 0; e < 4; e++) acc[i][j][e] = 0.0f;

    const int ntiles = K / BK;

    auto loadTile = [&](int bufi, int kt) {
        const int k0 = kt * BK;
        #pragma unroll
        for (int i = 0; i < 2; i++) {
            int e = tid * 2 + i;
            int r = e >> 2, c0 = (e & 3) * 8;
            cpa16(&As[bufi][r][c0], A + (size_t)(rowBase + r) * lda + k0 + c0);
        }
        #pragma unroll
        for (int i = 0; i < 2; i++) {
            int e = tid * 2 + i;
            int r = e >> 2, c0 = (e & 3) * 8;
            cpa16(&Bs[bufi][r][c0], Bt + (size_t)(colBase + r) * ldb + k0 + c0);
        }
        cpa_commit();
    };

    loadTile(0, 0);
    cpa_wait0();
    __syncthreads();

    for (int kt = 0; kt < ntiles; kt++) {
        int bufi = kt & 1;
        if (kt + 1 < ntiles) loadTile(bufi ^ 1, kt + 1);

        #pragma unroll
        for (int ks = 0; ks < 2; ks++) {
            const int kb = ks * 16;
            unsigned af[4][4], bf[4][2];
            #pragma unroll
            for (int mt = 0; mt < 4; mt++) {
                int r = wm * 64 + mt * 16 + group;
                const __half* base = &As[bufi][r][kb + 2 * tq];
                af[mt][0] = *reinterpret_cast<const unsigned*>(base);
                af[mt][1] = *reinterpret_cast<const unsigned*>(base + 8 * HPAD);
                af[mt][2] = *reinterpret_cast<const unsigned*>(base + 8);
                af[mt][3] = *reinterpret_cast<const unsigned*>(base + 8 * HPAD + 8);
            }
            #pragma unroll
            for (int nt = 0; nt < 4; nt++) {
                int n = wn * 32 + nt * 8 + group;
                const __half* base = &Bs[bufi][n][kb + 2 * tq];
                bf[nt][0] = *reinterpret_cast<const unsigned*>(base);
                bf[nt][1] = *reinterpret_cast<const unsigned*>(base + 8);
            }
            #pragma unroll
            for (int mt = 0; mt < 4; mt++)
                #pragma unroll
                for (int nt = 0; nt < 4; nt++)
                    mma_f16(acc[mt][nt], af[mt], bf[nt]);
        }

        if (kt + 1 < ntiles) cpa_wait0();
        __syncthreads();
    }

    #pragma unroll
    for (int mt = 0; mt < 4; mt++) {
        #pragma unroll
        for (int nt = 0; nt < 4; nt++) {
            int r = rowBase + wm * 64 + mt * 16 + group;
            int c = colBase + wn * 32 + nt * 8 + tq * 2;
            #pragma unroll
            for (int half_ = 0; half_ < 2; half_++) {
                int rr = r + half_ * 8;
                CT* crow = C + (size_t)rr * ldc;
                #pragma unroll
                for (int e = 0; e < 2; e++) {
                    int cc = c + e;
                    float v = acc[mt][nt][half_ * 2 + e];
                    v += bias[cc];
                    if (EPI == 2) v = v * normcdff(v);           // exact GELU
                    if (EPI == 3) v += res[(size_t)rr * ldc + cc];
                    storeC(&crow[cc], v);
                }
            }
        }
    }
}

// ---------------- launch ----------------
extern "C" void kernel_launch(void* const* d_in, const int* in_sizes, int n_in,
                              void* d_out, int out_size) {
    (void)in_sizes; (void)n_in; (void)out_size;
    const float* x     = (const float*)d_in[0];
    const float* qkv_w = (const float*)d_in[1];
    const float* qkv_b = (const float*)d_in[2];
    const float* out_w = (const float*)d_in[3];
    const float* out_b = (const float*)d_in[4];
    const float* ff1_w = (const float*)d_in[5];
    const float* ff1_b = (const float*)d_in[6];
    const float* ff2_w = (const float*)d_in[7];
    const float* ff2_b = (const float*)d_in[8];
    const float* ln1_g = (const float*)d_in[9];
    const float* ln1_b = (const float*)d_in[10];
    const float* ln2_g = (const float*)d_in[11];
    const float* ln2_b = (const float*)d_in[12];
    float* out = (float*)d_out;

    __half *pH, *pQKV, *pCtx, *pFFH, *pW;
    float *pX1, *pQB;
    cudaGetSymbolAddress((void**)&pH,   g_h);
    cudaGetSymbolAddress((void**)&pQKV, g_qkv);
    cudaGetSymbolAddress((void**)&pCtx, g_ctx);
    cudaGetSymbolAddress((void**)&pX1,  g_x1);
    cudaGetSymbolAddress((void**)&pFFH, g_ffh);
    cudaGetSymbolAddress((void**)&pW,   g_wt);
    cudaGetSymbolAddress((void**)&pQB,  g_qkvb);

    cudaFuncSetAttribute(flash_attn_kernel,
                         cudaFuncAttributeMaxDynamicSharedMemorySize, FA_SMEM);

    // 0) convert + transpose weights (Q columns of qkv_w scaled by 1/8)
    convt_kernel<<<dim3(3 * D_MODEL / 32, D_MODEL / 32), dim3(32, 8)>>>(
        qkv_w, pW + W_QKV, D_MODEL, 3 * D_MODEL, D_MODEL);
    convt_kernel<<<dim3(D_MODEL / 32, D_MODEL / 32), dim3(32, 8)>>>(
        out_w, pW + W_OUT, D_MODEL, D_MODEL, 0);
    convt_kernel<<<dim3(FF_HIDDEN / 32, D_MODEL / 32), dim3(32, 8)>>>(
        ff1_w, pW + W_FF1, D_MODEL, FF_HIDDEN, 0);
    convt_kernel<<<dim3(D_MODEL / 32, FF_HIDDEN / 32), dim3(32, 8)>>>(
        ff2_w, pW + W_FF2, FF_HIDDEN, D_MODEL, 0);
    scale_qbias_kernel<<<12, 256>>>(qkv_b, pQB);

    // 1) LN1 -> half h
    ln_kernel<<<M_ROWS, 256>>>(x, ln1_g, ln1_b, pH);

    // 2) QKV = h @ qkv_w + qkv_b (Q pre-scaled) -> half
    gemm_fp16<1, __half><<<dim3(3 * D_MODEL / BN, M_ROWS / BM), 256>>>(
        pH, D_MODEL, pW + W_QKV, D_MODEL, pQKV, 3 * D_MODEL,
        pQB, nullptr, M_ROWS, 3 * D_MODEL, D_MODEL);

    // 3) fused fp16 flash attention -> half ctx
    flash_attn_kernel<<<dim3(L_SEQ / 128, BATCH * NHEADS), 256, FA_SMEM>>>(
        pQKV, pCtx);

    // 4) x1 = ctx @ out_w + out_b + x
    gemm_fp16<3, float><<<dim3(D_MODEL / BN, M_ROWS / BM), 256>>>(
        pCtx, D_MODEL, pW + W_OUT, D_MODEL, pX1, D_MODEL,
        out_b, x, M_ROWS, D_MODEL, D_MODEL);

    // 5) LN2 -> half h
    ln_kernel<<<M_ROWS, 256>>>(pX1, ln2_g, ln2_b, pH);

    // 6) ffh = gelu(h @ ff1_w + ff1_b) -> half
    gemm_fp16<2, __half><<<dim3(FF_HIDDEN / BN, M_ROWS / BM), 256>>>(
        pH, D_MODEL, pW + W_FF1, D_MODEL, pFFH, FF_HIDDEN,
        ff1_b, nullptr, M_ROWS, FF_HIDDEN, D_MODEL);

    // 7) out = ffh @ ff2_w + ff2_b + x1
    gemm_fp16<3, float><<<dim3(D_MODEL / BN, M_ROWS / BM), 256>>>(
        pFFH, FF_HIDDEN, pW + W_FF2, FF_HIDDEN, out, D_MODEL,
        ff2_b, pX1, M_ROWS, D_MODEL, FF_HIDDEN);
}

// round 12
// speedup vs baseline: 2.3903x; 1.0244x over previous
#include <cuda_runtime.h>
#include <cuda_fp16.h>
#include <math.h>
#include <stdint.h>

// ---------------- problem constants ----------------
static constexpr int D_MODEL   = 1024;
static constexpr int L_SEQ     = 2048;
static constexpr int BATCH     = 4;
static constexpr int NHEADS    = 16;
static constexpr int HDIM      = 64;
static constexpr int FF_HIDDEN = 2048;
static constexpr int M_ROWS    = BATCH * L_SEQ;   // 8192

// ---------------- scratch (__device__ globals; no cudaMalloc allowed) ------
__device__ __half g_h  [(size_t)M_ROWS * D_MODEL];           // LN output (half)
__device__ __half g_qkv[(size_t)M_ROWS * 3 * D_MODEL];       // QKV (half)
__device__ __half g_ctx[(size_t)M_ROWS * D_MODEL];           // attention out (half)
__device__ float  g_x1 [(size_t)M_ROWS * D_MODEL];           // residual stream
__device__ __half g_ffh[(size_t)M_ROWS * FF_HIDDEN];         // gelu out (half)
__device__ float  g_qkvb[3 * D_MODEL];                       // qkv bias, Q part pre-scaled
// transposed half weights: qkv_w^T | out_w^T | ff1_w^T | ff2_w^T
static constexpr size_t W_QKV = 0;
static constexpr size_t W_OUT = W_QKV + (size_t)3 * D_MODEL * D_MODEL;
static constexpr size_t W_FF1 = W_OUT + (size_t)D_MODEL * D_MODEL;
static constexpr size_t W_FF2 = W_FF1 + (size_t)FF_HIDDEN * D_MODEL;
__device__ __half g_wt[W_FF2 + (size_t)D_MODEL * FF_HIDDEN];

// ------- weight convert+transpose: W[K,N] f32 -> Wt[N,K] half --------------
__global__ void convt_kernel(const float* __restrict__ W, __half* __restrict__ Wt,
                             int K, int N, int nScaleBelow) {
    __shared__ float t[32][33];
    int bx = blockIdx.x * 32, by = blockIdx.y * 32;
    int tx = threadIdx.x, ty = threadIdx.y;           // block (32,8)
    #pragma unroll
    for (int j = 0; j < 4; j++)
        t[ty + 8 * j][tx] = W[(size_t)(by + ty + 8 * j) * N + bx + tx];
    __syncthreads();
    #pragma unroll
    for (int j = 0; j < 4; j++) {
        int n = bx + ty + 8 * j;
        float v = t[tx][ty + 8 * j];
        if (n < nScaleBelow) v *= 0.125f;
        Wt[(size_t)n * K + by + tx] = __float2half_rn(v);
    }
}

__global__ void scale_qbias_kernel(const float* __restrict__ b, float* __restrict__ o) {
    int i = blockIdx.x * 256 + threadIdx.x;
    o[i] = b[i] * (i < D_MODEL ? 0.125f : 1.0f);
}

// ---------------- small helpers ----------------
__device__ __forceinline__ float blockSum256(float v) {
    __shared__ float sm[8];
    int lane = threadIdx.x & 31, w = threadIdx.x >> 5;
    #pragma unroll
    for (int o = 16; o; o >>= 1) v += __shfl_down_sync(0xffffffffu, v, o);
    if (lane == 0) sm[w] = v;
    __syncthreads();
    v = (threadIdx.x < 8) ? sm[threadIdx.x] : 0.0f;
    if (w == 0) {
        #pragma unroll
        for (int o = 4; o; o >>= 1) v += __shfl_down_sync(0xffffffffu, v, o);
        if (lane == 0) sm[0] = v;
    }
    __syncthreads();
    float r = sm[0];
    __syncthreads();
    return r;
}

// ---------------- LayerNorm ----------------
__global__ void ln_kernel(const float* __restrict__ x,
                          const float* __restrict__ gam,
                          const float* __restrict__ bet,
                          __half* __restrict__ out) {
    size_t row = blockIdx.x;
    const float4* xr = reinterpret_cast<const float4*>(x + row * D_MODEL);
    float4 v = xr[threadIdx.x];
    float s  = v.x + v.y + v.z + v.w;
    float sq = v.x*v.x + v.y*v.y + v.z*v.z + v.w*v.w;
    s  = blockSum256(s);
    sq = blockSum256(sq);
    float mu  = s * (1.0f / D_MODEL);
    float var = sq * (1.0f / D_MODEL) - mu * mu;
    float inv = rsqrtf(var + 1e-5f);
    float4 g4 = reinterpret_cast<const float4*>(gam)[threadIdx.x];
    float4 b4 = reinterpret_cast<const float4*>(bet)[threadIdx.x];
    __half2* orow = reinterpret_cast<__half2*>(out + row * D_MODEL);
    orow[2 * threadIdx.x]     = __floats2half2_rn((v.x - mu) * inv * g4.x + b4.x,
                                                  (v.y - mu) * inv * g4.y + b4.y);
    orow[2 * threadIdx.x + 1] = __floats2half2_rn((v.z - mu) * inv * g4.z + b4.z,
                                                  (v.w - mu) * inv * g4.w + b4.w);
}

// ---------------- cp.async / mma / ldmatrix helpers ----------------
__device__ __forceinline__ void cpa16(void* dst, const void* src) {
    unsigned d = (unsigned)__cvta_generic_to_shared(dst);
    asm volatile("cp.async.cg.shared.global [%0], [%1], 16;\n" :: "r"(d), "l"(src));
}
__device__ __forceinline__ void cpa_commit() { asm volatile("cp.async.commit_group;\n"); }
__device__ __forceinline__ void cpa_wait0()  { asm volatile("cp.async.wait_group 0;\n"); }
__device__ __forceinline__ void cpa_wait1()  { asm volatile("cp.async.wait_group 1;\n"); }

__device__ __forceinline__ void mma_f16(float* c, const unsigned* a, const unsigned* b) {
    asm volatile(
        "mma.sync.aligned.m16n8k16.row.col.f32.f16.f16.f32 "
        "{%0,%1,%2,%3},{%4,%5,%6,%7},{%8,%9},{%0,%1,%2,%3};"
        : "+f"(c[0]), "+f"(c[1]), "+f"(c[2]), "+f"(c[3])
        : "r"(a[0]), "r"(a[1]), "r"(a[2]), "r"(a[3]), "r"(b[0]), "r"(b[1]));
}

__device__ __forceinline__ void ldsm_x4(unsigned& r0, unsigned& r1,
                                        unsigned& r2, unsigned& r3, unsigned addr) {
    asm volatile("ldmatrix.sync.aligned.m8n8.x4.shared.b16 {%0,%1,%2,%3}, [%4];"
                 : "=r"(r0), "=r"(r1), "=r"(r2), "=r"(r3) : "r"(addr));
}
__device__ __forceinline__ void ldsm_x4_t(unsigned& r0, unsigned& r1,
                                          unsigned& r2, unsigned& r3, unsigned addr) {
    asm volatile("ldmatrix.sync.aligned.m8n8.x4.trans.shared.b16 {%0,%1,%2,%3}, [%4];"
                 : "=r"(r0), "=r"(r1), "=r"(r2), "=r"(r3) : "r"(addr));
}

// ============================================================================
// Fused flash attention, fp16 mma core (unchanged from R11).
// ============================================================================
static constexpr int KP = 72;
static constexpr int PP = 136;
static constexpr int FA_SMEM = (4 * 128 * KP + 128 * PP) * 2;   // 108544 B

__global__ __launch_bounds__(256, 1)
void flash_attn_kernel(const __half* __restrict__ qkv, __half* __restrict__ ctx) {
    extern __shared__ __half smemh[];
    __half* Ks = smemh;
    __half* Vs = smemh + 2 * 128 * KP;
    __half* Pb = smemh + 4 * 128 * KP;

    const int tid  = threadIdx.x;
    const int warp = tid >> 5, lane = tid & 31;
    const int group = lane >> 2, tq = lane & 3;

    const int bh = blockIdx.y;
    const int b = bh >> 4, h = bh & 15;
    const int q0 = blockIdx.x * 128;

    const __half* Qg = qkv + ((size_t)b * L_SEQ) * (3 * D_MODEL) + h * HDIM;
    const __half* Kg = Qg + D_MODEL;
    const __half* Vg = Qg + 2 * D_MODEL;

    #pragma unroll
    for (int i = 0; i < 4; i++) {
        int e = tid * 4 + i;
        int r = e >> 3, c0 = (e & 7) * 8;
        cpa16(&Pb[r * PP + c0], Qg + (size_t)(q0 + r) * (3 * D_MODEL) + c0);
    }
    auto loadKV = [&](int buf, int t) {
        const int k0 = t * 128;
        #pragma unroll
        for (int i = 0; i < 4; i++) {
            int e = tid * 4 + i;
            int r = e >> 3, c0 = (e & 7) * 8;
            cpa16(&Ks[buf * 128 * KP + r * KP + c0],
                  Kg + (size_t)(k0 + r) * (3 * D_MODEL) + c0);
            cpa16(&Vs[buf * 128 * KP + r * KP + c0],
                  Vg + (size_t)(k0 + r) * (3 * D_MODEL) + c0);
        }
    };
    loadKV(0, 0);
    cpa_commit();
    cpa_wait0();
    __syncthreads();

    unsigned qf[4][4];
    {
        const __half* Qw = Pb + (size_t)(warp * 16) * PP;
        #pragma unroll
        for (int kc = 0; kc < 4; kc++) {
            const __half* base = Qw + group * PP + kc * 16 + 2 * tq;
            qf[kc][0] = *reinterpret_cast<const unsigned*>(base);
            qf[kc][1] = *reinterpret_cast<const unsigned*>(base + 8 * PP);
            qf[kc][2] = *reinterpret_cast<const unsigned*>(base + 8);
            qf[kc][3] = *reinterpret_cast<const unsigned*>(base + 8 * PP + 8);
        }
    }
    __syncthreads();

    __half* Pw = Pb + (size_t)(warp * 16) * PP;

    const int krow = (lane & 7) + ((lane >> 4) << 3);
    const int kcol = lane & 8;
    const int vrow = lane & 15;
    const int vcol = (lane >> 4) << 3;
    const unsigned ks_base = (unsigned)__cvta_generic_to_shared(Ks);
    const unsigned vs_base = (unsigned)__cvta_generic_to_shared(Vs);

    float m0 = -INFINITY, m1 = -INFINITY, l0 = 0.0f, l1 = 0.0f;
    float acc_o[8][4];
    #pragma unroll
    for (int nt = 0; nt < 8; nt++)
        #pragma unroll
        for (int e = 0; e < 4; e++) acc_o[nt][e] = 0.0f;

    const int NT = L_SEQ / 128;
    for (int t = 0; t < NT; t++) {
        const int buf = t & 1;
        if (t + 1 < NT) { loadKV(buf ^ 1, t + 1); cpa_commit(); }

        const unsigned kb_base = ks_base + buf * 128 * KP * 2;
        const unsigned vb_base = vs_base + buf * 128 * KP * 2;

        float accs[16][4];
        #pragma unroll
        for (int nt = 0; nt < 16; nt++)
            #pragma unroll
            for (int e = 0; e < 4; e++) accs[nt][e] = 0.0f;

        #pragma unroll
        for (int ks = 0; ks < 4; ks++) {
            #pragma unroll
            for (int np = 0; np < 8; np++) {
                unsigned b0, b1, b2, b3;
                unsigned addr = kb_base +
                    ((np * 16 + krow) * KP + ks * 16 + kcol) * 2;
                ldsm_x4(b0, b1, b2, b3, addr);
                unsigned bA[2] = {b0, b1}, bB[2] = {b2, b3};
                mma_f16(accs[2 * np],     qf[ks], bA);
                mma_f16(accs[2 * np + 1], qf[ks], bB);
            }
        }

        float mt0 = -INFINITY, mt1 = -INFINITY;
        #pragma unroll
        for (int nt = 0; nt < 16; nt++) {
            mt0 = fmaxf(mt0, fmaxf(accs[nt][0], accs[nt][1]));
            mt1 = fmaxf(mt1, fmaxf(accs[nt][2], accs[nt][3]));
        }
        mt0 = fmaxf(mt0, __shfl_xor_sync(0xffffffffu, mt0, 1));
        mt0 = fmaxf(mt0, __shfl_xor_sync(0xffffffffu, mt0, 2));
        mt1 = fmaxf(mt1, __shfl_xor_sync(0xffffffffu, mt1, 1));
        mt1 = fmaxf(mt1, __shfl_xor_sync(0xffffffffu, mt1, 2));

        float mn0 = fmaxf(m0, mt0), mn1 = fmaxf(m1, mt1);
        float corr0 = __expf(m0 - mn0), corr1 = __expf(m1 - mn1);

        float rs0 = 0.0f, rs1 = 0.0f;
        #pragma unroll
        for (int nt = 0; nt < 16; nt++) {
            float p0 = __expf(accs[nt][0] - mn0);
            float p1 = __expf(accs[nt][1] - mn0);
            float p2 = __expf(accs[nt][2] - mn1);
            float p3 = __expf(accs[nt][3] - mn1);
            rs0 += p0 + p1;  rs1 += p2 + p3;
            int c = nt * 8 + tq * 2;
            *reinterpret_cast<__half2*>(&Pw[(group)     * PP + c]) = __floats2half2_rn(p0, p1);
            *reinterpret_cast<__half2*>(&Pw[(group + 8) * PP + c]) = __floats2half2_rn(p2, p3);
        }
        rs0 += __shfl_xor_sync(0xffffffffu, rs0, 1);
        rs0 += __shfl_xor_sync(0xffffffffu, rs0, 2);
        rs1 += __shfl_xor_sync(0xffffffffu, rs1, 1);
        rs1 += __shfl_xor_sync(0xffffffffu, rs1, 2);

        l0 = l0 * corr0 + rs0;
        l1 = l1 * corr1 + rs1;
        m0 = mn0; m1 = mn1;

        #pragma unroll
        for (int nt = 0; nt < 8; nt++) {
            acc_o[nt][0] *= corr0; acc_o[nt][1] *= corr0;
            acc_o[nt][2] *= corr1; acc_o[nt][3] *= corr1;
        }
        __syncwarp();

        #pragma unroll
        for (int kb = 0; kb < 8; kb++) {
            unsigned a[4];
            const __half* pbase = Pw + group * PP + kb * 16 + 2 * tq;
            a[0] = *reinterpret_cast<const unsigned*>(pbase);
            a[1] = *reinterpret_cast<const unsigned*>(pbase + 8 * PP);
            a[2] = *reinterpret_cast<const unsigned*>(pbase + 8);
            a[3] = *reinterpret_cast<const unsigned*>(pbase + 8 * PP + 8);
            #pragma unroll
            for (int np = 0; np < 4; np++) {
                unsigned b0, b1, b2, b3;
                unsigned addr = vb_base +
                    ((kb * 16 + vrow) * KP + np * 16 + vcol) * 2;
                ldsm_x4_t(b0, b1, b2, b3, addr);
                unsigned bA[2] = {b0, b1}, bB[2] = {b2, b3};
                mma_f16(acc_o[2 * np],     a, bA);
                mma_f16(acc_o[2 * np + 1], a, bB);
            }
        }
        __syncwarp();

        if (t + 1 < NT) cpa_wait0();
        __syncthreads();
    }

    float inv0 = 1.0f / l0, inv1 = 1.0f / l1;
    size_t orow0 = ((size_t)b * L_SEQ + q0 + warp * 16 + group) * D_MODEL + h * HDIM;
    size_t orow1 = orow0 + (size_t)8 * D_MODEL;
    #pragma unroll
    for (int nt = 0; nt < 8; nt++) {
        int d = nt * 8 + tq * 2;
        *reinterpret_cast<__half2*>(ctx + orow0 + d) =
            __floats2half2_rn(acc_o[nt][0] * inv0, acc_o[nt][1] * inv0);
        *reinterpret_cast<__half2*>(ctx + orow1 + d) =
            __floats2half2_rn(acc_o[nt][2] * inv1, acc_o[nt][3] * inv1);
    }
}

// ---------------- FP16 GEMM, 128x256 CTA, 64x64 warp tile, ldmatrix --------
// C[M,N] = A @ Bt^T (+ bias) (+ gelu | + residual)
// A [M,K] half; Bt [N,K] half. N % 256 == 0, K % 32 == 0, M % 128 == 0.
static constexpr int BM = 128, BN = 256, BK = 32;
static constexpr int HPAD = 40;                     // halfs per smem row
static constexpr int G_ASTG = BM * HPAD;            // A stage stride (halfs)
static constexpr int G_BSTG = BN * HPAD;            // B stage stride
static constexpr int G_SMEM = 3 * (G_ASTG + G_BSTG) * 2;   // 92160 B

__device__ __forceinline__ void storeC2(float* p, float v0, float v1) {
    *reinterpret_cast<float2*>(p) = make_float2(v0, v1);
}
__device__ __forceinline__ void storeC2(__half* p, float v0, float v1) {
    *reinterpret_cast<__half2*>(p) = __floats2half2_rn(v0, v1);
}

template <int EPI, typename CT>
__global__ __launch_bounds__(256, 1)
void gemm_fp16(const __half* __restrict__ A, int lda,
               const __half* __restrict__ Bt, int ldb,
               CT* __restrict__ C, int ldc,
               const float* __restrict__ bias, const float* __restrict__ res,
               int M, int N, int K) {
    extern __shared__ __half gsm[];
    __half* As = gsm;                       // [3][BM][HPAD]
    __half* Bs = gsm + 3 * G_ASTG;          // [3][BN][HPAD]

    const int tid  = threadIdx.x;
    const int warp = tid >> 5, lane = tid & 31;
    const int wm = warp >> 2, wn = warp & 3;       // 2 x 4 grid of 64x64 tiles
    const int group = lane >> 2, tq = lane & 3;
    const int rowBase = blockIdx.y * BM;
    const int colBase = blockIdx.x * BN;

    // ldmatrix per-lane offsets
    const int arow = lane & 15;                    // A: m-row within 16
    const int acol = ((lane >> 4) & 1) * 8;        // A: k-chunk select
    const int brow = (lane & 7) + ((lane >> 4) << 3);  // B: n-row within 16
    const int bcol = lane & 8;                     // B: k-chunk select
    const unsigned as_base = (unsigned)__cvta_generic_to_shared(As);
    const unsigned bs_base = (unsigned)__cvta_generic_to_shared(Bs);

    float acc[4][8][4];
    #pragma unroll
    for (int i = 0; i < 4; i++)
        #pragma unroll
        for (int j = 0; j < 8; j++)
            #pragma unroll
            for (int e = 0; e < 4; e++) acc[i][j][e] = 0.0f;

    const int ntiles = K / BK;

    auto loadTile = [&](int st, int kt) {
        const int k0 = kt * BK;
        #pragma unroll
        for (int i = 0; i < 2; i++) {              // A: 128 rows x 4 chunks
            int e = tid * 2 + i;
            int r = e >> 2, c0 = (e & 3) * 8;
            cpa16(&As[st * G_ASTG + r * HPAD + c0],
                  A + (size_t)(rowBase + r) * lda + k0 + c0);
        }
        #pragma unroll
        for (int i = 0; i < 4; i++) {              // B: 256 rows x 4 chunks
            int e = tid * 4 + i;
            int r = e >> 2, c0 = (e & 3) * 8;
            cpa16(&Bs[st * G_BSTG + r * HPAD + c0],
                  Bt + (size_t)(colBase + r) * ldb + k0 + c0);
        }
        cpa_commit();
    };

    loadTile(0, 0);
    loadTile(1, 1);
    cpa_wait1();
    __syncthreads();

    for (int kt = 0; kt < ntiles; kt++) {
        const int st = kt % 3;
        const unsigned a_st = as_base + st * G_ASTG * 2;
        const unsigned b_st = bs_base + st * G_BSTG * 2;

        #pragma unroll
        for (int ks = 0; ks < 2; ks++) {
            const int kb = ks * 16;
            unsigned af[4][4];
            #pragma unroll
            for (int mt = 0; mt < 4; mt++) {
                int r = wm * 64 + mt * 16 + arow;
                ldsm_x4(af[mt][0], af[mt][1], af[mt][2], af[mt][3],
                        a_st + (r * HPAD + kb + acol) * 2);
            }
            #pragma unroll
            for (int np = 0; np < 4; np++) {       // 4 n16 pairs = 64 cols
                unsigned b0, b1, b2, b3;
                int n = wn * 64 + np * 16 + brow;
                ldsm_x4(b0, b1, b2, b3, b_st + (n * HPAD + kb + bcol) * 2);
                unsigned bA[2] = {b0, b1}, bB[2] = {b2, b3};
                #pragma unroll
                for (int mt = 0; mt < 4; mt++) {
                    mma_f16(acc[mt][2 * np],     af[mt], bA);
                    mma_f16(acc[mt][2 * np + 1], af[mt], bB);
                }
            }
        }

        if (kt + 2 < ntiles) {
            loadTile((kt + 2) % 3, kt + 2);
            cpa_wait1();
        } else {
            cpa_wait0();
        }
        __syncthreads();
    }

    // ---------------- epilogue ----------------
    #pragma unroll
    for (int mt = 0; mt < 4; mt++) {
        #pragma unroll
        for (int nt = 0; nt < 8; nt++) {
            int r = rowBase + wm * 64 + mt * 16 + group;
            int c = colBase + wn * 64 + nt * 8 + tq * 2;
            float b0 = bias[c], b1 = bias[c + 1];
            #pragma unroll
            for (int half_ = 0; half_ < 2; half_++) {
                int rr = r + half_ * 8;
                float v0 = acc[mt][nt][half_ * 2]     + b0;
                float v1 = acc[mt][nt][half_ * 2 + 1] + b1;
                if (EPI == 2) { v0 = v0 * normcdff(v0); v1 = v1 * normcdff(v1); }
                if (EPI == 3) {
                    float2 rv = *reinterpret_cast<const float2*>(res + (size_t)rr * ldc + c);
                    v0 += rv.x; v1 += rv.y;
                }
                storeC2(&C[(size_t)rr * ldc + c], v0, v1);
            }
        }
    }
}

// ---------------- launch ----------------
extern "C" void kernel_launch(void* const* d_in, const int* in_sizes, int n_in,
                              void* d_out, int out_size) {
    (void)in_sizes; (void)n_in; (void)out_size;
    const float* x     = (const float*)d_in[0];
    const float* qkv_w = (const float*)d_in[1];
    const float* qkv_b = (const float*)d_in[2];
    const float* out_w = (const float*)d_in[3];
    const float* out_b = (const float*)d_in[4];
    const float* ff1_w = (const float*)d_in[5];
    const float* ff1_b = (const float*)d_in[6];
    const float* ff2_w = (const float*)d_in[7];
    const float* ff2_b = (const float*)d_in[8];
    const float* ln1_g = (const float*)d_in[9];
    const float* ln1_b = (const float*)d_in[10];
    const float* ln2_g = (const float*)d_in[11];
    const float* ln2_b = (const float*)d_in[12];
    float* out = (float*)d_out;

    __half *pH, *pQKV, *pCtx, *pFFH, *pW;
    float *pX1, *pQB;
    cudaGetSymbolAddress((void**)&pH,   g_h);
    cudaGetSymbolAddress((void**)&pQKV, g_qkv);
    cudaGetSymbolAddress((void**)&pCtx, g_ctx);
    cudaGetSymbolAddress((void**)&pX1,  g_x1);
    cudaGetSymbolAddress((void**)&pFFH, g_ffh);
    cudaGetSymbolAddress((void**)&pW,   g_wt);
    cudaGetSymbolAddress((void**)&pQB,  g_qkvb);

    cudaFuncSetAttribute(flash_attn_kernel,
                         cudaFuncAttributeMaxDynamicSharedMemorySize, FA_SMEM);
    cudaFuncSetAttribute(gemm_fp16<1, __half>,
                         cudaFuncAttributeMaxDynamicSharedMemorySize, G_SMEM);
    cudaFuncSetAttribute(gemm_fp16<2, __half>,
                         cudaFuncAttributeMaxDynamicSharedMemorySize, G_SMEM);
    cudaFuncSetAttribute(gemm_fp16<3, float>,
                         cudaFuncAttributeMaxDynamicSharedMemorySize, G_SMEM);

    // 0) convert + transpose weights (Q columns of qkv_w scaled by 1/8)
    convt_kernel<<<dim3(3 * D_MODEL / 32, D_MODEL / 32), dim3(32, 8)>>>(
        qkv_w, pW + W_QKV, D_MODEL, 3 * D_MODEL, D_MODEL);
    convt_kernel<<<dim3(D_MODEL / 32, D_MODEL / 32), dim3(32, 8)>>>(
        out_w, pW + W_OUT, D_MODEL, D_MODEL, 0);
    convt_kernel<<<dim3(FF_HIDDEN / 32, D_MODEL / 32), dim3(32, 8)>>>(
        ff1_w, pW + W_FF1, D_MODEL, FF_HIDDEN, 0);
    convt_kernel<<<dim3(D_MODEL / 32, FF_HIDDEN / 32), dim3(32, 8)>>>(
        ff2_w, pW + W_FF2, FF_HIDDEN, D_MODEL, 0);
    scale_qbias_kernel<<<12, 256>>>(qkv_b, pQB);

    // 1) LN1 -> half h
    ln_kernel<<<M_ROWS, 256>>>(x, ln1_g, ln1_b, pH);

    // 2) QKV = h @ qkv_w + qkv_b (Q pre-scaled) -> half
    gemm_fp16<1, __half><<<dim3(3 * D_MODEL / BN, M_ROWS / BM), 256, G_SMEM>>>(
        pH, D_MODEL, pW + W_QKV, D_MODEL, pQKV, 3 * D_MODEL,
        pQB, nullptr, M_ROWS, 3 * D_MODEL, D_MODEL);

    // 3) fused fp16 flash attention -> half ctx
    flash_attn_kernel<<<dim3(L_SEQ / 128, BATCH * NHEADS), 256, FA_SMEM>>>(
        pQKV, pCtx);

    // 4) x1 = ctx @ out_w + out_b + x
    gemm_fp16<3, float><<<dim3(D_MODEL / BN, M_ROWS / BM), 256, G_SMEM>>>(
        pCtx, D_MODEL, pW + W_OUT, D_MODEL, pX1, D_MODEL,
        out_b, x, M_ROWS, D_MODEL, D_MODEL);

    // 5) LN2 -> half h
    ln_kernel<<<M_ROWS, 256>>>(pX1, ln2_g, ln2_b, pH);

    // 6) ffh = gelu(h @ ff1_w + ff1_b) -> half
    gemm_fp16<2, __half><<<dim3(FF_HIDDEN / BN, M_ROWS / BM), 256, G_SMEM>>>(
        pH, D_MODEL, pW + W_FF1, D_MODEL, pFFH, FF_HIDDEN,
        ff1_b, nullptr, M_ROWS, FF_HIDDEN, D_MODEL);

    // 7) out = ffh @ ff2_w + ff2_b + x1
    gemm_fp16<3, float><<<dim3(D_MODEL / BN, M_ROWS / BM), 256, G_SMEM>>>(
        pFFH, FF_HIDDEN, pW + W_FF2, FF_HIDDEN, out, D_MODEL,
        ff2_b, pX1, M_ROWS, D_MODEL, FF_HIDDEN);
}